// round 1
// baseline (speedup 1.0000x reference)
#include <cuda_runtime.h>
#include <cstdint>

#define B_  4
#define S_  2048
#define D_  1024
#define H_  16
#define HD_ 64

// Scratch: Q,K,V,O in [B,H,S,HD] layout (bh-major)
__device__ float g_q[B_*H_*S_*HD_];
__device__ float g_k[B_*H_*S_*HD_];
__device__ float g_v[B_*H_*S_*HD_];
__device__ float g_o[B_*H_*S_*HD_];

// ---------------------------------------------------------------------------
// Kernel 1: fused QKV projection.  C[M=8192, N=3072] = X[8192,1024] @ W
// W columns: n = p*1024 + h*64 + e, weight element W_p[h][d][e].
// Tile 128x128, BK=8, 256 threads, 8x8 microtile.
// ---------------------------------------------------------------------------
__global__ __launch_bounds__(256, 2)
void qkv_kernel(const float* __restrict__ x,
                const float* __restrict__ Wq,
                const float* __restrict__ Wk,
                const float* __restrict__ Wv) {
    __shared__ float As[8][128];
    __shared__ float Bs[8][128];

    const int tid = threadIdx.x;
    const int tx = tid & 15, ty = tid >> 4;
    const int n0 = blockIdx.x * 128;   // 0..2944
    const int m0 = blockIdx.y * 128;   // 0..8064

    const int p = n0 >> 10;  // which projection (tile never crosses: 1024%128==0)
    const float* W = (p == 0) ? Wq : ((p == 1) ? Wk : Wv);
    const int nrem = n0 & 1023;

    // A loader: row = tid>>1 (0..127), ak = (tid&1)*4
    const int arow = tid >> 1;
    const int ak   = (tid & 1) * 4;
    const float* Aptr = x + (size_t)(m0 + arow) * D_ + ak;

    // B loader: kb = tid>>5 (0..7), bn = (tid&31)*4 (0..124)
    const int kb = tid >> 5;
    const int bn = (tid & 31) * 4;
    const int nb_g = nrem + bn;
    const int bh_ = nb_g >> 6;
    const int be  = nb_g & 63;
    const float* Bptr = W + (size_t)bh_ * (D_ * HD_) + (size_t)kb * HD_ + be;

    float c[8][8];
#pragma unroll
    for (int i = 0; i < 8; i++)
#pragma unroll
        for (int j = 0; j < 8; j++) c[i][j] = 0.f;

    for (int kt = 0; kt < D_ / 8; kt++) {
        float4 a = *(const float4*)(Aptr + kt * 8);
        float4 b = *(const float4*)(Bptr + (size_t)kt * 8 * HD_);
        __syncthreads();
        As[ak + 0][arow] = a.x;
        As[ak + 1][arow] = a.y;
        As[ak + 2][arow] = a.z;
        As[ak + 3][arow] = a.w;
        *(float4*)&Bs[kb][bn] = b;
        __syncthreads();
#pragma unroll
        for (int k = 0; k < 8; k++) {
            float4 a0 = *(float4*)&As[k][ty * 8];
            float4 a1 = *(float4*)&As[k][ty * 8 + 4];
            float4 b0 = *(float4*)&Bs[k][tx * 8];
            float4 b1 = *(float4*)&Bs[k][tx * 8 + 4];
            float ar[8] = {a0.x, a0.y, a0.z, a0.w, a1.x, a1.y, a1.z, a1.w};
            float br[8] = {b0.x, b0.y, b0.z, b0.w, b1.x, b1.y, b1.z, b1.w};
#pragma unroll
            for (int i = 0; i < 8; i++)
#pragma unroll
                for (int j = 0; j < 8; j++) c[i][j] = fmaf(ar[i], br[j], c[i][j]);
        }
    }

    // Store to g_q/g_k/g_v in [B,H,S,HD]
    float* Og = (p == 0) ? g_q : ((p == 1) ? g_k : g_v);
#pragma unroll
    for (int i = 0; i < 8; i++) {
        const int m = m0 + ty * 8 + i;
        const int bb = m >> 11, ss = m & 2047;
#pragma unroll
        for (int j4 = 0; j4 < 8; j4 += 4) {
            const int n = n0 + tx * 8 + j4;
            const int h = (n & 1023) >> 6;
            const int e = n & 63;
            float4 v = make_float4(c[i][j4], c[i][j4 + 1], c[i][j4 + 2], c[i][j4 + 3]);
            *(float4*)(Og + (((size_t)(bb * H_ + h) * S_ + ss) * HD_ + e)) = v;
        }
    }
}

// ---------------------------------------------------------------------------
// Kernel 2: causal flash attention, fp32.
// BM=BN=64, HD=64, 256 threads (16x16), 4x4 microtile.
// Smem layouts (row stride R=68): Qs[e][r], Ks[e][c], Vs[c][d], Ps[c][r]
//  -> all compute-phase LDS are float4 & conflict-free.
// ---------------------------------------------------------------------------
#define R_ 68
#define ATTN_SMEM (4 * 64 * R_ * sizeof(float))

__global__ __launch_bounds__(256, 2)
void attn_kernel() {
    extern __shared__ float sm[];
    float* Qs = sm;
    float* Ks = sm + 64 * R_;
    float* Vs = sm + 2 * 64 * R_;
    float* Ps = sm + 3 * 64 * R_;

    const int tid = threadIdx.x;
    const int tx = tid & 15, ty = tid >> 4;
    const int bq = blockIdx.x;        // query tile
    const int bh = blockIdx.y;        // b*H + h
    const int q0 = bq * 64;

    const float* Qg = g_q + (size_t)bh * S_ * HD_;
    const float* Kg = g_k + (size_t)bh * S_ * HD_;
    const float* Vg = g_v + (size_t)bh * S_ * HD_;
    float*       Og = g_o + (size_t)bh * S_ * HD_;

    // Load Q tile transposed, pre-scaled by 1/sqrt(HD)
#pragma unroll
    for (int i = 0; i < 4; i++) {
        const int idx = tid + i * 256;
        const int r = idx >> 4;
        const int e = (idx & 15) * 4;
        float4 v = *(const float4*)(Qg + (size_t)(q0 + r) * HD_ + e);
        Qs[(e + 0) * R_ + r] = v.x * 0.125f;
        Qs[(e + 1) * R_ + r] = v.y * 0.125f;
        Qs[(e + 2) * R_ + r] = v.z * 0.125f;
        Qs[(e + 3) * R_ + r] = v.w * 0.125f;
    }

    float m[4], l[4], acc[4][4];
#pragma unroll
    for (int i = 0; i < 4; i++) {
        m[i] = -1e30f; l[i] = 0.f;
#pragma unroll
        for (int j = 0; j < 4; j++) acc[i][j] = 0.f;
    }

    for (int kt = 0; kt <= bq; kt++) {
        const int k0 = kt * 64;
        __syncthreads();  // prior-iter reads done (also fences Q load on kt=0)
        // Load K (transposed) and V (direct)
#pragma unroll
        for (int i = 0; i < 4; i++) {
            const int idx = tid + i * 256;
            const int r = idx >> 4;
            const int e = (idx & 15) * 4;
            float4 kv = *(const float4*)(Kg + (size_t)(k0 + r) * HD_ + e);
            Ks[(e + 0) * R_ + r] = kv.x;
            Ks[(e + 1) * R_ + r] = kv.y;
            Ks[(e + 2) * R_ + r] = kv.z;
            Ks[(e + 3) * R_ + r] = kv.w;
            float4 vv = *(const float4*)(Vg + (size_t)(k0 + r) * HD_ + e);
            *(float4*)(Vs + r * R_ + e) = vv;
        }
        __syncthreads();

        // S = Q @ K^T  (4x4 per thread)
        float s[4][4];
#pragma unroll
        for (int i = 0; i < 4; i++)
#pragma unroll
            for (int j = 0; j < 4; j++) s[i][j] = 0.f;
#pragma unroll 8
        for (int e = 0; e < 64; e++) {
            float4 q4 = *(float4*)(Qs + e * R_ + ty * 4);
            float4 k4 = *(float4*)(Ks + e * R_ + tx * 4);
            float qr[4] = {q4.x, q4.y, q4.z, q4.w};
            float kr[4] = {k4.x, k4.y, k4.z, k4.w};
#pragma unroll
            for (int i = 0; i < 4; i++)
#pragma unroll
                for (int j = 0; j < 4; j++) s[i][j] = fmaf(qr[i], kr[j], s[i][j]);
        }

        // Causal mask (only diagonal tile)
        if (kt == bq) {
#pragma unroll
            for (int i = 0; i < 4; i++)
#pragma unroll
                for (int j = 0; j < 4; j++)
                    if (tx * 4 + j > ty * 4 + i) s[i][j] = -1e30f;
        }

        // Online softmax per row (rows split by ty, reduce across tx lanes)
#pragma unroll
        for (int i = 0; i < 4; i++) {
            float rm = fmaxf(fmaxf(s[i][0], s[i][1]), fmaxf(s[i][2], s[i][3]));
#pragma unroll
            for (int off = 1; off < 16; off <<= 1)
                rm = fmaxf(rm, __shfl_xor_sync(0xffffffffu, rm, off));
            const float mn = fmaxf(m[i], rm);
            const float corr = __expf(m[i] - mn);
            m[i] = mn;
            float rs = 0.f;
#pragma unroll
            for (int j = 0; j < 4; j++) {
                s[i][j] = __expf(s[i][j] - mn);
                rs += s[i][j];
            }
#pragma unroll
            for (int off = 1; off < 16; off <<= 1)
                rs += __shfl_xor_sync(0xffffffffu, rs, off);
            l[i] = l[i] * corr + rs;
#pragma unroll
            for (int j = 0; j < 4; j++) acc[i][j] *= corr;
        }

        // Write P transposed: Ps[c][r]
#pragma unroll
        for (int j = 0; j < 4; j++) {
            float4 pv = make_float4(s[0][j], s[1][j], s[2][j], s[3][j]);
            *(float4*)(Ps + (tx * 4 + j) * R_ + ty * 4) = pv;
        }
        __syncthreads();

        // O += P @ V
#pragma unroll 8
        for (int c = 0; c < 64; c++) {
            float4 p4 = *(float4*)(Ps + c * R_ + ty * 4);
            float4 v4 = *(float4*)(Vs + c * R_ + tx * 4);
            float pr[4] = {p4.x, p4.y, p4.z, p4.w};
            float vr[4] = {v4.x, v4.y, v4.z, v4.w};
#pragma unroll
            for (int i = 0; i < 4; i++)
#pragma unroll
                for (int j = 0; j < 4; j++) acc[i][j] = fmaf(pr[i], vr[j], acc[i][j]);
        }
    }

    // Epilogue
#pragma unroll
    for (int i = 0; i < 4; i++) {
        const float inv = 1.0f / l[i];
        float4 v = make_float4(acc[i][0] * inv, acc[i][1] * inv,
                               acc[i][2] * inv, acc[i][3] * inv);
        *(float4*)(Og + (size_t)(q0 + ty * 4 + i) * HD_ + tx * 4) = v;
    }
}

// ---------------------------------------------------------------------------
// Kernel 3: output projection. out[m][n] = sum_k A[m][k]*Wo[n][k] + bo[n]
// A[m][k] = g_o[((b*H + k/64)*S + s)*64 + k%64]   (head-concat transpose fused)
// ---------------------------------------------------------------------------
__global__ __launch_bounds__(256, 2)
void oproj_kernel(const float* __restrict__ Wo,
                  const float* __restrict__ bo,
                  float* __restrict__ out) {
    __shared__ float As[8][128];
    __shared__ float Bs[8][128];

    const int tid = threadIdx.x;
    const int tx = tid & 15, ty = tid >> 4;
    const int n0 = blockIdx.x * 128;   // 0..896
    const int m0 = blockIdx.y * 128;

    const int arow = tid >> 1;
    const int ak   = (tid & 1) * 4;
    const int am = m0 + arow;
    const int abb = am >> 11, ass = am & 2047;

    const int brow = tid >> 1;         // n within tile, 0..127
    const int bk   = (tid & 1) * 4;
    const float* Bptr = Wo + (size_t)(n0 + brow) * D_ + bk;

    float c[8][8];
#pragma unroll
    for (int i = 0; i < 8; i++)
#pragma unroll
        for (int j = 0; j < 8; j++) c[i][j] = 0.f;

    for (int kt = 0; kt < D_ / 8; kt++) {
        const int kg = kt * 8 + ak;
        const int hh = kg >> 6, ee = kg & 63;
        float4 a = *(const float4*)(g_o + (((size_t)(abb * H_ + hh) * S_ + ass) * HD_ + ee));
        float4 b = *(const float4*)(Bptr + kt * 8);
        __syncthreads();
        As[ak + 0][arow] = a.x;
        As[ak + 1][arow] = a.y;
        As[ak + 2][arow] = a.z;
        As[ak + 3][arow] = a.w;
        Bs[bk + 0][brow] = b.x;
        Bs[bk + 1][brow] = b.y;
        Bs[bk + 2][brow] = b.z;
        Bs[bk + 3][brow] = b.w;
        __syncthreads();
#pragma unroll
        for (int k = 0; k < 8; k++) {
            float4 a0 = *(float4*)&As[k][ty * 8];
            float4 a1 = *(float4*)&As[k][ty * 8 + 4];
            float4 b0 = *(float4*)&Bs[k][tx * 8];
            float4 b1 = *(float4*)&Bs[k][tx * 8 + 4];
            float ar[8] = {a0.x, a0.y, a0.z, a0.w, a1.x, a1.y, a1.z, a1.w};
            float br[8] = {b0.x, b0.y, b0.z, b0.w, b1.x, b1.y, b1.z, b1.w};
#pragma unroll
            for (int i = 0; i < 8; i++)
#pragma unroll
                for (int j = 0; j < 8; j++) c[i][j] = fmaf(ar[i], br[j], c[i][j]);
        }
    }

#pragma unroll
    for (int i = 0; i < 8; i++) {
        const int mm = m0 + ty * 8 + i;
#pragma unroll
        for (int j4 = 0; j4 < 8; j4 += 4) {
            const int nn = n0 + tx * 8 + j4;
            float4 v = make_float4(c[i][j4 + 0] + bo[nn + 0],
                                   c[i][j4 + 1] + bo[nn + 1],
                                   c[i][j4 + 2] + bo[nn + 2],
                                   c[i][j4 + 3] + bo[nn + 3]);
            *(float4*)(out + (size_t)mm * D_ + nn) = v;
        }
    }
}

// ---------------------------------------------------------------------------
extern "C" void kernel_launch(void* const* d_in, const int* in_sizes, int n_in,
                              void* d_out, int out_size) {
    const float* x  = (const float*)d_in[0];
    const float* Wq = (const float*)d_in[1];
    const float* Wk = (const float*)d_in[2];
    const float* Wv = (const float*)d_in[3];
    const float* Wo = (const float*)d_in[4];
    const float* bo = (const float*)d_in[5];
    float* out = (float*)d_out;

    cudaFuncSetAttribute(attn_kernel, cudaFuncAttributeMaxDynamicSharedMemorySize,
                         (int)ATTN_SMEM);

    qkv_kernel<<<dim3(24, 64), 256>>>(x, Wq, Wk, Wv);
    attn_kernel<<<dim3(S_ / 64, B_ * H_), 256, ATTN_SMEM>>>();
    oproj_kernel<<<dim3(8, 64), 256>>>(Wo, bo, out);
}

// round 4
// speedup vs baseline: 1.5491x; 1.5491x over previous
#include <cuda_runtime.h>
#include <cuda_bf16.h>
#include <cstdint>

#define B_  4
#define S_  2048
#define D_  1024
#define H_  16
#define HD_ 64
#define M_TOT (B_*S_)     // 8192
#define NQKV  3072
#define KDIM  1024

// ---------------------------------------------------------------------------
// Device scratch
// ---------------------------------------------------------------------------
__device__ float g_q[(size_t)B_*H_*S_*HD_];
__device__ float g_k[(size_t)B_*H_*S_*HD_];
__device__ float g_v[(size_t)B_*H_*S_*HD_];
__device__ __nv_bfloat16 g_xhi[(size_t)M_TOT*KDIM];
__device__ __nv_bfloat16 g_xlo[(size_t)M_TOT*KDIM];
__device__ __nv_bfloat16 g_wqkv_hi[(size_t)NQKV*KDIM];   // [n][k] K-major
__device__ __nv_bfloat16 g_wqkv_lo[(size_t)NQKV*KDIM];
__device__ __nv_bfloat16 g_wo_hi[(size_t)D_*KDIM];
__device__ __nv_bfloat16 g_wo_lo[(size_t)D_*KDIM];
__device__ __nv_bfloat16 g_aohi[(size_t)M_TOT*KDIM];     // attention out, [m][k]
__device__ __nv_bfloat16 g_aolo[(size_t)M_TOT*KDIM];

// ---------------------------------------------------------------------------
// Portable PTX helpers (sm_80+ ISA only — no sm_100a-gated features)
// ---------------------------------------------------------------------------
__device__ __forceinline__ uint32_t smem_u32(const void* p) {
    uint32_t a;
    asm("{ .reg .u64 t; cvta.to.shared.u64 t, %1; cvt.u32.u64 %0, t; }"
        : "=r"(a) : "l"(p));
    return a;
}

__device__ __forceinline__ void cp16(uint32_t dst, const void* src) {
    asm volatile("cp.async.cg.shared.global [%0], [%1], 16;"
                 :: "r"(dst), "l"(src) : "memory");
}
#define CP_COMMIT() asm volatile("cp.async.commit_group;" ::: "memory")
#define CP_WAIT2()  asm volatile("cp.async.wait_group 2;"  ::: "memory")

__device__ __forceinline__ void ldsm4(uint32_t& r0, uint32_t& r1,
                                      uint32_t& r2, uint32_t& r3, uint32_t addr) {
    asm volatile("ldmatrix.sync.aligned.m8n8.x4.shared.b16 {%0,%1,%2,%3}, [%4];"
                 : "=r"(r0), "=r"(r1), "=r"(r2), "=r"(r3) : "r"(addr));
}

__device__ __forceinline__ void mma16816(float* c,
                                         uint32_t a0, uint32_t a1, uint32_t a2, uint32_t a3,
                                         uint32_t b0, uint32_t b1) {
    asm volatile(
        "mma.sync.aligned.m16n8k16.row.col.f32.bf16.bf16.f32 "
        "{%0,%1,%2,%3}, {%4,%5,%6,%7}, {%8,%9}, {%0,%1,%2,%3};"
        : "+f"(c[0]), "+f"(c[1]), "+f"(c[2]), "+f"(c[3])
        : "r"(a0), "r"(a1), "r"(a2), "r"(a3), "r"(b0), "r"(b1));
}

// ---------------------------------------------------------------------------
// Conversion kernels: fp32 -> bf16 hi/lo
// ---------------------------------------------------------------------------
__device__ __forceinline__ void split_bf16(float v, __nv_bfloat16& hi, __nv_bfloat16& lo) {
    hi = __float2bfloat16(v);
    lo = __float2bfloat16(v - __bfloat162float(hi));
}

__global__ void conv_x_kernel(const float* __restrict__ src) {
    size_t i = ((size_t)blockIdx.x * 256 + threadIdx.x) * 4;
    float4 v = *(const float4*)(src + i);
    __nv_bfloat16 h, l;
    split_bf16(v.x, h, l); g_xhi[i+0] = h; g_xlo[i+0] = l;
    split_bf16(v.y, h, l); g_xhi[i+1] = h; g_xlo[i+1] = l;
    split_bf16(v.z, h, l); g_xhi[i+2] = h; g_xlo[i+2] = l;
    split_bf16(v.w, h, l); g_xhi[i+3] = h; g_xlo[i+3] = l;
}

__global__ void conv_wo_kernel(const float* __restrict__ src) {
    size_t i = ((size_t)blockIdx.x * 256 + threadIdx.x) * 4;
    float4 v = *(const float4*)(src + i);
    __nv_bfloat16 h, l;
    split_bf16(v.x, h, l); g_wo_hi[i+0] = h; g_wo_lo[i+0] = l;
    split_bf16(v.y, h, l); g_wo_hi[i+1] = h; g_wo_lo[i+1] = l;
    split_bf16(v.z, h, l); g_wo_hi[i+2] = h; g_wo_lo[i+2] = l;
    split_bf16(v.w, h, l); g_wo_hi[i+3] = h; g_wo_lo[i+3] = l;
}

// Wq/Wk/Wv [H][D][HD] -> g_wqkv [n=p*1024+h*64+e][k=d], transposed via smem
__global__ void conv_wqkv_kernel(const float* __restrict__ Wq,
                                 const float* __restrict__ Wk,
                                 const float* __restrict__ Wv) {
    __shared__ float t[64][65];
    const int p = blockIdx.z, h = blockIdx.y, d0 = blockIdx.x * 64;
    const float* W = (p == 0) ? Wq : ((p == 1) ? Wk : Wv);
    const float* Wh = W + (size_t)h * D_ * HD_;
    const int tid = threadIdx.x;
#pragma unroll
    for (int j = 0; j < 16; j++) {
        int idx = tid + j * 256;
        int d = idx >> 6, e = idx & 63;
        t[d][e] = Wh[(size_t)(d0 + d) * HD_ + e];
    }
    __syncthreads();
#pragma unroll
    for (int j = 0; j < 16; j++) {
        int idx = tid + j * 256;
        int e = idx >> 6, d = idx & 63;
        float v = t[d][e];
        __nv_bfloat16 hi, lo;
        split_bf16(v, hi, lo);
        size_t out = (size_t)(p * 1024 + h * 64 + e) * KDIM + d0 + d;
        g_wqkv_hi[out] = hi;
        g_wqkv_lo[out] = lo;
    }
}

// ---------------------------------------------------------------------------
// bf16x3 GEMM via mma.sync.m16n8k16 (portable tensor-core path).
// C[m][n] = sum_k A[m][k] * B[n][k],  A/B pre-split into bf16 hi+lo.
// CTA tile 128x128x32, 8 warps (2x4), warp tile 64x32, 4-stage cp.async.
// mode 0: A = x, B = wqkv -> scatter fp32 into g_q/g_k/g_v
// mode 1: A = attn out, B = wo -> d_out + bias
// ---------------------------------------------------------------------------
#define ARR_B     10240           // 128 rows x 80B padded stride
#define STAGE_B   (4 * ARR_B)     // Ahi, Alo, Bhi, Blo
#define GEMM_SMEM (4 * STAGE_B)   // 163840 bytes (4 stages)

__global__ __launch_bounds__(256)
void gemm_mma(float* __restrict__ outp, const float* __restrict__ bias, int mode) {
    extern __shared__ __align__(128) char smem[];
    const uint32_t sb = smem_u32(smem);
    const int tid = threadIdx.x;
    const int warp = tid >> 5, lane = tid & 31;
    const int wm = warp >> 2, wn = warp & 3;
    const int m0 = blockIdx.y * 128, n0 = blockIdx.x * 128;

    const __nv_bfloat16* Ahi = mode ? g_aohi : g_xhi;
    const __nv_bfloat16* Alo = mode ? g_aolo : g_xlo;
    const __nv_bfloat16* Bhi = mode ? g_wo_hi : g_wqkv_hi;
    const __nv_bfloat16* Blo = mode ? g_wo_lo : g_wqkv_lo;

    // ---- loader slots: 2 rows per thread per array (16B chunks) ----
    const int lr = tid >> 2;            // 0..63
    const int lc = tid & 3;             // 0..3 (16B column)
    const size_t gA0 = (size_t)(m0 + lr) * KDIM + lc * 8;
    const size_t gA1 = gA0 + (size_t)64 * KDIM;
    const size_t gB0 = (size_t)(n0 + lr) * KDIM + lc * 8;
    const size_t gB1 = gB0 + (size_t)64 * KDIM;
    const uint32_t so0 = (uint32_t)lr * 80 + (uint32_t)lc * 16;
    const uint32_t so1 = so0 + 64 * 80;

#define LOAD_STAGE(st, kel) do { \
    uint32_t b_ = sb + (uint32_t)(st) * STAGE_B; \
    cp16(b_ +              so0, Ahi + gA0 + (kel)); \
    cp16(b_ +              so1, Ahi + gA1 + (kel)); \
    cp16(b_ +     ARR_B  + so0, Alo + gA0 + (kel)); \
    cp16(b_ +     ARR_B  + so1, Alo + gA1 + (kel)); \
    cp16(b_ + 2 * ARR_B  + so0, Bhi + gB0 + (kel)); \
    cp16(b_ + 2 * ARR_B  + so1, Bhi + gB1 + (kel)); \
    cp16(b_ + 3 * ARR_B  + so0, Blo + gB0 + (kel)); \
    cp16(b_ + 3 * ARR_B  + so1, Blo + gB1 + (kel)); \
} while (0)

    LOAD_STAGE(0, 0);  CP_COMMIT();
    LOAD_STAGE(1, 32); CP_COMMIT();
    LOAD_STAGE(2, 64); CP_COMMIT();

    // ---- ldmatrix per-lane offsets ----
    // A: 16x16 frag, lanes 0-15 -> rows, lanes 16-31 -> +8 cols (k)
    const uint32_t aoff = (uint32_t)(wm * 64 + (lane & 15)) * 80 + (uint32_t)(lane >> 4) * 16;
    // B: [n][k] rows; r0/r1 = n0..7 (k0,k8), r2/r3 = n8..15
    const uint32_t boff = (uint32_t)(wn * 32 + (lane & 7) + ((lane >> 4) & 1) * 8) * 80
                        + (uint32_t)((lane >> 3) & 1) * 16;

    float c[4][4][4];
#pragma unroll
    for (int i = 0; i < 4; i++)
#pragma unroll
        for (int j = 0; j < 4; j++)
#pragma unroll
            for (int r = 0; r < 4; r++) c[i][j][r] = 0.f;

    for (int ck = 0; ck < 32; ck++) {
        CP_WAIT2();
        __syncthreads();
        const uint32_t base = sb + (uint32_t)(ck & 3) * STAGE_B;
        if (ck + 3 < 32) LOAD_STAGE((ck + 3) & 3, (size_t)(ck + 3) * 32);
        CP_COMMIT();

#pragma unroll
        for (int kk = 0; kk < 2; kk++) {
            uint32_t ah[4][4], al[4][4], bh[4][2], bl[4][2];
#pragma unroll
            for (int i = 0; i < 4; i++) {
                ldsm4(ah[i][0], ah[i][1], ah[i][2], ah[i][3],
                      base + aoff + i * 1280 + kk * 32);
                ldsm4(al[i][0], al[i][1], al[i][2], al[i][3],
                      base + ARR_B + aoff + i * 1280 + kk * 32);
            }
#pragma unroll
            for (int p = 0; p < 2; p++) {
                uint32_t r0, r1, r2, r3;
                ldsm4(r0, r1, r2, r3, base + 2 * ARR_B + boff + p * 1280 + kk * 32);
                bh[2*p][0] = r0; bh[2*p][1] = r1; bh[2*p+1][0] = r2; bh[2*p+1][1] = r3;
                ldsm4(r0, r1, r2, r3, base + 3 * ARR_B + boff + p * 1280 + kk * 32);
                bl[2*p][0] = r0; bl[2*p][1] = r1; bl[2*p+1][0] = r2; bl[2*p+1][1] = r3;
            }
#pragma unroll
            for (int i = 0; i < 4; i++)
#pragma unroll
                for (int j = 0; j < 4; j++) {
                    mma16816(c[i][j], ah[i][0], ah[i][1], ah[i][2], ah[i][3],
                             bh[j][0], bh[j][1]);
                    mma16816(c[i][j], ah[i][0], ah[i][1], ah[i][2], ah[i][3],
                             bl[j][0], bl[j][1]);
                    mma16816(c[i][j], al[i][0], al[i][1], al[i][2], al[i][3],
                             bh[j][0], bh[j][1]);
                }
        }
    }

    // ---- epilogue: C-frag rows = l>>2 (+8), cols = (l&3)*2 (+1) ----
#pragma unroll
    for (int i = 0; i < 4; i++) {
#pragma unroll
        for (int j = 0; j < 4; j++) {
            const int ncol = n0 + wn * 32 + j * 8 + (lane & 3) * 2;
#pragma unroll
            for (int half = 0; half < 2; half++) {
                const int row = m0 + wm * 64 + i * 16 + (lane >> 2) + half * 8;
                float2 v = make_float2(c[i][j][half * 2], c[i][j][half * 2 + 1]);
                if (mode == 0) {
                    const int p = ncol >> 10;
                    float* T = (p == 0) ? g_q : ((p == 1) ? g_k : g_v);
                    const int h = (ncol & 1023) >> 6;
                    const int e = ncol & 63;
                    const int bb = row >> 11, ss = row & 2047;
                    *(float2*)(T + (((size_t)(bb * H_ + h) * S_ + ss) * HD_ + e)) = v;
                } else {
                    float2 bv = *(const float2*)(bias + ncol);
                    v.x += bv.x; v.y += bv.y;
                    *(float2*)(outp + (size_t)row * D_ + ncol) = v;
                }
            }
        }
    }
#undef LOAD_STAGE
}

// ---------------------------------------------------------------------------
// Causal flash attention, fp32 SIMT (R1-verified); epilogue writes bf16 hi/lo
// ---------------------------------------------------------------------------
#define R_ 68
#define ATTN_SMEM (4 * 64 * R_ * sizeof(float))

__global__ __launch_bounds__(256, 2)
void attn_kernel() {
    extern __shared__ float sm[];
    float* Qs = sm;
    float* Ks = sm + 64 * R_;
    float* Vs = sm + 2 * 64 * R_;
    float* Ps = sm + 3 * 64 * R_;

    const int tid = threadIdx.x;
    const int tx = tid & 15, ty = tid >> 4;
    const int bq = blockIdx.x;
    const int bh = blockIdx.y;
    const int q0 = bq * 64;

    const float* Qg = g_q + (size_t)bh * S_ * HD_;
    const float* Kg = g_k + (size_t)bh * S_ * HD_;
    const float* Vg = g_v + (size_t)bh * S_ * HD_;

#pragma unroll
    for (int i = 0; i < 4; i++) {
        const int idx = tid + i * 256;
        const int r = idx >> 4;
        const int e = (idx & 15) * 4;
        float4 v = *(const float4*)(Qg + (size_t)(q0 + r) * HD_ + e);
        Qs[(e + 0) * R_ + r] = v.x * 0.125f;
        Qs[(e + 1) * R_ + r] = v.y * 0.125f;
        Qs[(e + 2) * R_ + r] = v.z * 0.125f;
        Qs[(e + 3) * R_ + r] = v.w * 0.125f;
    }

    float m[4], l[4], acc[4][4];
#pragma unroll
    for (int i = 0; i < 4; i++) {
        m[i] = -1e30f; l[i] = 0.f;
#pragma unroll
        for (int j = 0; j < 4; j++) acc[i][j] = 0.f;
    }

    for (int kt = 0; kt <= bq; kt++) {
        const int k0 = kt * 64;
        __syncthreads();
#pragma unroll
        for (int i = 0; i < 4; i++) {
            const int idx = tid + i * 256;
            const int r = idx >> 4;
            const int e = (idx & 15) * 4;
            float4 kv = *(const float4*)(Kg + (size_t)(k0 + r) * HD_ + e);
            Ks[(e + 0) * R_ + r] = kv.x;
            Ks[(e + 1) * R_ + r] = kv.y;
            Ks[(e + 2) * R_ + r] = kv.z;
            Ks[(e + 3) * R_ + r] = kv.w;
            float4 vv = *(const float4*)(Vg + (size_t)(k0 + r) * HD_ + e);
            *(float4*)(Vs + r * R_ + e) = vv;
        }
        __syncthreads();

        float s[4][4];
#pragma unroll
        for (int i = 0; i < 4; i++)
#pragma unroll
            for (int j = 0; j < 4; j++) s[i][j] = 0.f;
#pragma unroll 8
        for (int e = 0; e < 64; e++) {
            float4 q4 = *(float4*)(Qs + e * R_ + ty * 4);
            float4 k4 = *(float4*)(Ks + e * R_ + tx * 4);
            float qr[4] = {q4.x, q4.y, q4.z, q4.w};
            float kr[4] = {k4.x, k4.y, k4.z, k4.w};
#pragma unroll
            for (int i = 0; i < 4; i++)
#pragma unroll
                for (int j = 0; j < 4; j++) s[i][j] = fmaf(qr[i], kr[j], s[i][j]);
        }

        if (kt == bq) {
#pragma unroll
            for (int i = 0; i < 4; i++)
#pragma unroll
                for (int j = 0; j < 4; j++)
                    if (tx * 4 + j > ty * 4 + i) s[i][j] = -1e30f;
        }

#pragma unroll
        for (int i = 0; i < 4; i++) {
            float rm = fmaxf(fmaxf(s[i][0], s[i][1]), fmaxf(s[i][2], s[i][3]));
#pragma unroll
            for (int off = 1; off < 16; off <<= 1)
                rm = fmaxf(rm, __shfl_xor_sync(0xffffffffu, rm, off));
            const float mn = fmaxf(m[i], rm);
            const float corr = __expf(m[i] - mn);
            m[i] = mn;
            float rs = 0.f;
#pragma unroll
            for (int j = 0; j < 4; j++) {
                s[i][j] = __expf(s[i][j] - mn);
                rs += s[i][j];
            }
#pragma unroll
            for (int off = 1; off < 16; off <<= 1)
                rs += __shfl_xor_sync(0xffffffffu, rs, off);
            l[i] = l[i] * corr + rs;
#pragma unroll
            for (int j = 0; j < 4; j++) acc[i][j] *= corr;
        }

#pragma unroll
        for (int j = 0; j < 4; j++) {
            float4 pv = make_float4(s[0][j], s[1][j], s[2][j], s[3][j]);
            *(float4*)(Ps + (tx * 4 + j) * R_ + ty * 4) = pv;
        }
        __syncthreads();

#pragma unroll 8
        for (int cc = 0; cc < 64; cc++) {
            float4 p4 = *(float4*)(Ps + cc * R_ + ty * 4);
            float4 v4 = *(float4*)(Vs + cc * R_ + tx * 4);
            float pr[4] = {p4.x, p4.y, p4.z, p4.w};
            float vr[4] = {v4.x, v4.y, v4.z, v4.w};
#pragma unroll
            for (int i = 0; i < 4; i++)
#pragma unroll
                for (int j = 0; j < 4; j++) acc[i][j] = fmaf(pr[i], vr[j], acc[i][j]);
        }
    }

    // Epilogue: [m = b*S + s][k = h*64 + e] bf16 hi/lo for oproj GEMM
    const int b = bh >> 4, h = bh & 15;
#pragma unroll
    for (int i = 0; i < 4; i++) {
        const float inv = 1.0f / l[i];
        const size_t base = (size_t)(b * S_ + q0 + ty * 4 + i) * KDIM + h * 64 + tx * 4;
#pragma unroll
        for (int j = 0; j < 4; j++) {
            const float v = acc[i][j] * inv;
            __nv_bfloat16 hi, lo;
            split_bf16(v, hi, lo);
            g_aohi[base + j] = hi;
            g_aolo[base + j] = lo;
        }
    }
}

// ---------------------------------------------------------------------------
extern "C" void kernel_launch(void* const* d_in, const int* in_sizes, int n_in,
                              void* d_out, int out_size) {
    const float* x  = (const float*)d_in[0];
    const float* Wq = (const float*)d_in[1];
    const float* Wk = (const float*)d_in[2];
    const float* Wv = (const float*)d_in[3];
    const float* Wo = (const float*)d_in[4];
    const float* bo = (const float*)d_in[5];
    float* out = (float*)d_out;

    cudaFuncSetAttribute(gemm_mma, cudaFuncAttributeMaxDynamicSharedMemorySize,
                         (int)GEMM_SMEM);
    cudaFuncSetAttribute(attn_kernel, cudaFuncAttributeMaxDynamicSharedMemorySize,
                         (int)ATTN_SMEM);

    conv_x_kernel<<<(M_TOT * KDIM) / (256 * 4), 256>>>(x);
    conv_wqkv_kernel<<<dim3(16, 16, 3), 256>>>(Wq, Wk, Wv);
    conv_wo_kernel<<<(D_ * KDIM) / (256 * 4), 256>>>(Wo);

    gemm_mma<<<dim3(NQKV / 128, M_TOT / 128), 256, GEMM_SMEM>>>(nullptr, nullptr, 0);
    attn_kernel<<<dim3(S_ / 64, B_ * H_), 256, ATTN_SMEM>>>();
    gemm_mma<<<dim3(D_ / 128, M_TOT / 128), 256, GEMM_SMEM>>>(out, bo, 1);
}

// round 5
// speedup vs baseline: 2.6704x; 1.7238x over previous
#include <cuda_runtime.h>
#include <cuda_bf16.h>
#include <cstdint>

#define B_  4
#define S_  2048
#define D_  1024
#define H_  16
#define HD_ 64
#define M_TOT (B_*S_)     // 8192
#define NQKV  3072
#define KDIM  1024

// ---------------------------------------------------------------------------
// Device scratch (all bf16 hi/lo pairs)
// ---------------------------------------------------------------------------
__device__ __nv_bfloat16 g_xhi[(size_t)M_TOT*KDIM];
__device__ __nv_bfloat16 g_xlo[(size_t)M_TOT*KDIM];
__device__ __nv_bfloat16 g_wqkv_hi[(size_t)NQKV*KDIM];   // [n][k] K-major
__device__ __nv_bfloat16 g_wqkv_lo[(size_t)NQKV*KDIM];
__device__ __nv_bfloat16 g_wo_hi[(size_t)D_*KDIM];
__device__ __nv_bfloat16 g_wo_lo[(size_t)D_*KDIM];
__device__ __nv_bfloat16 g_qhi[(size_t)B_*H_*S_*HD_];    // [b,h,s,e], Q pre-scaled
__device__ __nv_bfloat16 g_qlo[(size_t)B_*H_*S_*HD_];
__device__ __nv_bfloat16 g_khi[(size_t)B_*H_*S_*HD_];
__device__ __nv_bfloat16 g_klo[(size_t)B_*H_*S_*HD_];
__device__ __nv_bfloat16 g_vhi[(size_t)B_*H_*S_*HD_];
__device__ __nv_bfloat16 g_vlo[(size_t)B_*H_*S_*HD_];
__device__ __nv_bfloat16 g_aohi[(size_t)M_TOT*KDIM];     // attention out [m][k]
__device__ __nv_bfloat16 g_aolo[(size_t)M_TOT*KDIM];

// ---------------------------------------------------------------------------
// Portable PTX helpers (sm_80+ ISA only)
// ---------------------------------------------------------------------------
__device__ __forceinline__ uint32_t smem_u32(const void* p) {
    uint32_t a;
    asm("{ .reg .u64 t; cvta.to.shared.u64 t, %1; cvt.u32.u64 %0, t; }"
        : "=r"(a) : "l"(p));
    return a;
}

__device__ __forceinline__ void cp16(uint32_t dst, const void* src) {
    asm volatile("cp.async.cg.shared.global [%0], [%1], 16;"
                 :: "r"(dst), "l"(src) : "memory");
}
#define CP_COMMIT() asm volatile("cp.async.commit_group;" ::: "memory")
#define CP_WAIT2()  asm volatile("cp.async.wait_group 2;"  ::: "memory")
#define CP_WAIT1()  asm volatile("cp.async.wait_group 1;"  ::: "memory")

__device__ __forceinline__ void ldsm4(uint32_t& r0, uint32_t& r1,
                                      uint32_t& r2, uint32_t& r3, uint32_t addr) {
    asm volatile("ldmatrix.sync.aligned.m8n8.x4.shared.b16 {%0,%1,%2,%3}, [%4];"
                 : "=r"(r0), "=r"(r1), "=r"(r2), "=r"(r3) : "r"(addr));
}
__device__ __forceinline__ void ldsm4t(uint32_t& r0, uint32_t& r1,
                                       uint32_t& r2, uint32_t& r3, uint32_t addr) {
    asm volatile("ldmatrix.sync.aligned.m8n8.x4.trans.shared.b16 {%0,%1,%2,%3}, [%4];"
                 : "=r"(r0), "=r"(r1), "=r"(r2), "=r"(r3) : "r"(addr));
}

__device__ __forceinline__ void mma16816(float* c,
                                         uint32_t a0, uint32_t a1, uint32_t a2, uint32_t a3,
                                         uint32_t b0, uint32_t b1) {
    asm volatile(
        "mma.sync.aligned.m16n8k16.row.col.f32.bf16.bf16.f32 "
        "{%0,%1,%2,%3}, {%4,%5,%6,%7}, {%8,%9}, {%0,%1,%2,%3};"
        : "+f"(c[0]), "+f"(c[1]), "+f"(c[2]), "+f"(c[3])
        : "r"(a0), "r"(a1), "r"(a2), "r"(a3), "r"(b0), "r"(b1));
}

__device__ __forceinline__ void split_bf16(float v, __nv_bfloat16& hi, __nv_bfloat16& lo) {
    hi = __float2bfloat16(v);
    lo = __float2bfloat16(v - __bfloat162float(hi));
}
__device__ __forceinline__ uint32_t pack2(__nv_bfloat16 a, __nv_bfloat16 b) {
    __nv_bfloat162 t; t.x = a; t.y = b;
    return *(uint32_t*)&t;
}

// ---------------------------------------------------------------------------
// Conversion kernels
// ---------------------------------------------------------------------------
__global__ void conv_x_kernel(const float* __restrict__ src) {
    size_t i = ((size_t)blockIdx.x * 256 + threadIdx.x) * 4;
    float4 v = *(const float4*)(src + i);
    __nv_bfloat16 h, l;
    split_bf16(v.x, h, l); g_xhi[i+0] = h; g_xlo[i+0] = l;
    split_bf16(v.y, h, l); g_xhi[i+1] = h; g_xlo[i+1] = l;
    split_bf16(v.z, h, l); g_xhi[i+2] = h; g_xlo[i+2] = l;
    split_bf16(v.w, h, l); g_xhi[i+3] = h; g_xlo[i+3] = l;
}

__global__ void conv_wo_kernel(const float* __restrict__ src) {
    size_t i = ((size_t)blockIdx.x * 256 + threadIdx.x) * 4;
    float4 v = *(const float4*)(src + i);
    __nv_bfloat16 h, l;
    split_bf16(v.x, h, l); g_wo_hi[i+0] = h; g_wo_lo[i+0] = l;
    split_bf16(v.y, h, l); g_wo_hi[i+1] = h; g_wo_lo[i+1] = l;
    split_bf16(v.z, h, l); g_wo_hi[i+2] = h; g_wo_lo[i+2] = l;
    split_bf16(v.w, h, l); g_wo_hi[i+3] = h; g_wo_lo[i+3] = l;
}

__global__ void conv_wqkv_kernel(const float* __restrict__ Wq,
                                 const float* __restrict__ Wk,
                                 const float* __restrict__ Wv) {
    __shared__ float t[64][65];
    const int p = blockIdx.z, h = blockIdx.y, d0 = blockIdx.x * 64;
    const float* W = (p == 0) ? Wq : ((p == 1) ? Wk : Wv);
    const float* Wh = W + (size_t)h * D_ * HD_;
    const int tid = threadIdx.x;
#pragma unroll
    for (int j = 0; j < 16; j++) {
        int idx = tid + j * 256;
        int d = idx >> 6, e = idx & 63;
        t[d][e] = Wh[(size_t)(d0 + d) * HD_ + e];
    }
    __syncthreads();
#pragma unroll
    for (int j = 0; j < 16; j++) {
        int idx = tid + j * 256;
        int e = idx >> 6, d = idx & 63;
        float v = t[d][e];
        __nv_bfloat16 hi, lo;
        split_bf16(v, hi, lo);
        size_t out = (size_t)(p * 1024 + h * 64 + e) * KDIM + d0 + d;
        g_wqkv_hi[out] = hi;
        g_wqkv_lo[out] = lo;
    }
}

// ---------------------------------------------------------------------------
// bf16x3 GEMM via mma.sync.m16n8k16 (verified R4).
// mode 0: x @ wqkv -> bf16 hi/lo Q (scaled 0.125) / K / V in [b,h,s,e]
// mode 1: attn-out @ wo -> d_out + bias (fp32)
// ---------------------------------------------------------------------------
#define ARR_B     10240
#define STAGE_B   (4 * ARR_B)
#define GEMM_SMEM (4 * STAGE_B)   // 163840

__global__ __launch_bounds__(256)
void gemm_mma(float* __restrict__ outp, const float* __restrict__ bias, int mode) {
    extern __shared__ __align__(128) char smem[];
    const uint32_t sb = smem_u32(smem);
    const int tid = threadIdx.x;
    const int warp = tid >> 5, lane = tid & 31;
    const int wm = warp >> 2, wn = warp & 3;
    const int m0 = blockIdx.y * 128, n0 = blockIdx.x * 128;

    const __nv_bfloat16* Ahi = mode ? g_aohi : g_xhi;
    const __nv_bfloat16* Alo = mode ? g_aolo : g_xlo;
    const __nv_bfloat16* Bhi = mode ? g_wo_hi : g_wqkv_hi;
    const __nv_bfloat16* Blo = mode ? g_wo_lo : g_wqkv_lo;

    const int lr = tid >> 2;
    const int lc = tid & 3;
    const size_t gA0 = (size_t)(m0 + lr) * KDIM + lc * 8;
    const size_t gA1 = gA0 + (size_t)64 * KDIM;
    const size_t gB0 = (size_t)(n0 + lr) * KDIM + lc * 8;
    const size_t gB1 = gB0 + (size_t)64 * KDIM;
    const uint32_t so0 = (uint32_t)lr * 80 + (uint32_t)lc * 16;
    const uint32_t so1 = so0 + 64 * 80;

#define LOAD_STAGE(st, kel) do { \
    uint32_t b_ = sb + (uint32_t)(st) * STAGE_B; \
    cp16(b_ +              so0, Ahi + gA0 + (kel)); \
    cp16(b_ +              so1, Ahi + gA1 + (kel)); \
    cp16(b_ +     ARR_B  + so0, Alo + gA0 + (kel)); \
    cp16(b_ +     ARR_B  + so1, Alo + gA1 + (kel)); \
    cp16(b_ + 2 * ARR_B  + so0, Bhi + gB0 + (kel)); \
    cp16(b_ + 2 * ARR_B  + so1, Bhi + gB1 + (kel)); \
    cp16(b_ + 3 * ARR_B  + so0, Blo + gB0 + (kel)); \
    cp16(b_ + 3 * ARR_B  + so1, Blo + gB1 + (kel)); \
} while (0)

    LOAD_STAGE(0, 0);  CP_COMMIT();
    LOAD_STAGE(1, 32); CP_COMMIT();
    LOAD_STAGE(2, 64); CP_COMMIT();

    const uint32_t aoff = (uint32_t)(wm * 64 + (lane & 15)) * 80 + (uint32_t)(lane >> 4) * 16;
    const uint32_t boff = (uint32_t)(wn * 32 + (lane & 7) + ((lane >> 4) & 1) * 8) * 80
                        + (uint32_t)((lane >> 3) & 1) * 16;

    float c[4][4][4];
#pragma unroll
    for (int i = 0; i < 4; i++)
#pragma unroll
        for (int j = 0; j < 4; j++)
#pragma unroll
            for (int r = 0; r < 4; r++) c[i][j][r] = 0.f;

    for (int ck = 0; ck < 32; ck++) {
        CP_WAIT2();
        __syncthreads();
        const uint32_t base = sb + (uint32_t)(ck & 3) * STAGE_B;
        if (ck + 3 < 32) LOAD_STAGE((ck + 3) & 3, (size_t)(ck + 3) * 32);
        CP_COMMIT();

#pragma unroll
        for (int kk = 0; kk < 2; kk++) {
            uint32_t ah[4][4], al[4][4], bh[4][2], bl[4][2];
#pragma unroll
            for (int i = 0; i < 4; i++) {
                ldsm4(ah[i][0], ah[i][1], ah[i][2], ah[i][3],
                      base + aoff + i * 1280 + kk * 32);
                ldsm4(al[i][0], al[i][1], al[i][2], al[i][3],
                      base + ARR_B + aoff + i * 1280 + kk * 32);
            }
#pragma unroll
            for (int p = 0; p < 2; p++) {
                uint32_t r0, r1, r2, r3;
                ldsm4(r0, r1, r2, r3, base + 2 * ARR_B + boff + p * 1280 + kk * 32);
                bh[2*p][0] = r0; bh[2*p][1] = r1; bh[2*p+1][0] = r2; bh[2*p+1][1] = r3;
                ldsm4(r0, r1, r2, r3, base + 3 * ARR_B + boff + p * 1280 + kk * 32);
                bl[2*p][0] = r0; bl[2*p][1] = r1; bl[2*p+1][0] = r2; bl[2*p+1][1] = r3;
            }
#pragma unroll
            for (int i = 0; i < 4; i++)
#pragma unroll
                for (int j = 0; j < 4; j++) {
                    mma16816(c[i][j], ah[i][0], ah[i][1], ah[i][2], ah[i][3],
                             bh[j][0], bh[j][1]);
                    mma16816(c[i][j], ah[i][0], ah[i][1], ah[i][2], ah[i][3],
                             bl[j][0], bl[j][1]);
                    mma16816(c[i][j], al[i][0], al[i][1], al[i][2], al[i][3],
                             bh[j][0], bh[j][1]);
                }
        }
    }

#pragma unroll
    for (int i = 0; i < 4; i++) {
#pragma unroll
        for (int j = 0; j < 4; j++) {
            const int ncol = n0 + wn * 32 + j * 8 + (lane & 3) * 2;
#pragma unroll
            for (int half = 0; half < 2; half++) {
                const int row = m0 + wm * 64 + i * 16 + (lane >> 2) + half * 8;
                float vx = c[i][j][half * 2], vy = c[i][j][half * 2 + 1];
                if (mode == 0) {
                    const int p = ncol >> 10;
                    const float sc = (p == 0) ? 0.125f : 1.0f;
                    __nv_bfloat16* Th = (p == 0) ? g_qhi : ((p == 1) ? g_khi : g_vhi);
                    __nv_bfloat16* Tl = (p == 0) ? g_qlo : ((p == 1) ? g_klo : g_vlo);
                    const int h = (ncol & 1023) >> 6;
                    const int e = ncol & 63;
                    const int bb = row >> 11, ss = row & 2047;
                    __nv_bfloat16 hx, lx, hy, ly;
                    split_bf16(vx * sc, hx, lx);
                    split_bf16(vy * sc, hy, ly);
                    const size_t off = ((size_t)(bb * H_ + h) * S_ + ss) * HD_ + e;
                    *(uint32_t*)(Th + off) = pack2(hx, hy);
                    *(uint32_t*)(Tl + off) = pack2(lx, ly);
                } else {
                    float2 bv = *(const float2*)(bias + ncol);
                    float2 v = make_float2(vx + bv.x, vy + bv.y);
                    *(float2*)(outp + (size_t)row * D_ + ncol) = v;
                }
            }
        }
    }
#undef LOAD_STAGE
}

// ---------------------------------------------------------------------------
// Tensor-core causal flash attention (bf16x3 on both GEMMs).
// BM=128 (8 warps x 16-row strip), BN=64. Q frags resident in registers.
// Smem rows padded to 144 B -> conflict-free ldmatrix.
// ---------------------------------------------------------------------------
#define AT_LDB  144                  // bytes per 64-elem bf16 row (+16 pad)
#define AT_KSZ  (64 * AT_LDB)        // 9216 per 64x64 array
#define AT_STAGE (4 * AT_KSZ)        // Khi,Klo,Vhi,Vlo
#define AT_Q    (2 * 128 * AT_LDB)   // Qhi+Qlo tiles: 36864
#define AT_SMEM (AT_Q + 2 * AT_STAGE) // 110592

__global__ __launch_bounds__(256, 1)
void attn_mma() {
    extern __shared__ __align__(128) char smc[];
    const uint32_t sb = smem_u32(smc);
    const int tid = threadIdx.x;
    const int warp = tid >> 5, lane = tid & 31;
    const int bq = blockIdx.x, bh = blockIdx.y;
    const int q0 = bq * 128;

    const __nv_bfloat16* Qh = g_qhi + (size_t)bh * S_ * HD_;
    const __nv_bfloat16* Ql = g_qlo + (size_t)bh * S_ * HD_;
    const __nv_bfloat16* Kh = g_khi + (size_t)bh * S_ * HD_;
    const __nv_bfloat16* Kl = g_klo + (size_t)bh * S_ * HD_;
    const __nv_bfloat16* Vh = g_vhi + (size_t)bh * S_ * HD_;
    const __nv_bfloat16* Vl = g_vlo + (size_t)bh * S_ * HD_;

    // ---- Q tile load (hi+lo) ----
#pragma unroll
    for (int i = 0; i < 4; i++) {
        int idx = tid + i * 256;
        int r = idx >> 3, ch = idx & 7;
        size_t g = (size_t)(q0 + r) * HD_ + ch * 8;
        cp16(sb + r * AT_LDB + ch * 16, Qh + g);
        cp16(sb + 128 * AT_LDB + r * AT_LDB + ch * 16, Ql + g);
    }
    CP_COMMIT();

    const int ktmax = 2 * bq + 1;

#define LOAD_KV(kt, st) do { \
    uint32_t kb_ = sb + AT_Q + (uint32_t)(st) * AT_STAGE; \
    int t0_ = (kt) * 64; \
    _Pragma("unroll") \
    for (int i_ = 0; i_ < 2; i_++) { \
        int idx_ = tid + i_ * 256; \
        int r_ = idx_ >> 3, ch_ = idx_ & 7; \
        size_t g_ = (size_t)(t0_ + r_) * HD_ + ch_ * 8; \
        uint32_t s_ = (uint32_t)r_ * AT_LDB + (uint32_t)ch_ * 16; \
        cp16(kb_ + s_,              Kh + g_); \
        cp16(kb_ +     AT_KSZ + s_, Kl + g_); \
        cp16(kb_ + 2 * AT_KSZ + s_, Vh + g_); \
        cp16(kb_ + 3 * AT_KSZ + s_, Vl + g_); \
    } } while (0)

    LOAD_KV(0, 0); CP_COMMIT();
    CP_WAIT1();          // Q group done (groups complete in order)
    __syncthreads();

    // ---- Q fragments (resident) ----
    uint32_t qh[4][4], ql[4][4];
    const uint32_t aoff = (uint32_t)(warp * 16 + (lane & 15)) * AT_LDB
                        + (uint32_t)(lane >> 4) * 16;
#pragma unroll
    for (int ks = 0; ks < 4; ks++) {
        ldsm4(qh[ks][0], qh[ks][1], qh[ks][2], qh[ks][3], sb + aoff + ks * 32);
        ldsm4(ql[ks][0], ql[ks][1], ql[ks][2], ql[ks][3],
              sb + 128 * AT_LDB + aoff + ks * 32);
    }
    if (1 <= ktmax) LOAD_KV(1, 1);
    CP_COMMIT();

    float oacc[8][4];
#pragma unroll
    for (int j = 0; j < 8; j++)
#pragma unroll
        for (int r = 0; r < 4; r++) oacc[j][r] = 0.f;
    float mrow[2] = {-1e30f, -1e30f};
    float lrow[2] = {0.f, 0.f};

    const int rg = q0 + warp * 16 + (lane >> 2);   // row of frag-half 0

    for (int kt = 0; kt <= ktmax; kt++) {
        CP_WAIT1();
        __syncthreads();
        const uint32_t kb = sb + AT_Q + (uint32_t)(kt & 1) * AT_STAGE;

        // ---- S = Q K^T (bf16x3) ----
        float sfr[8][4];
#pragma unroll
        for (int j = 0; j < 8; j++)
#pragma unroll
            for (int r = 0; r < 4; r++) sfr[j][r] = 0.f;

#pragma unroll
        for (int nb = 0; nb < 4; nb++) {
            const uint32_t brow = (uint32_t)(nb * 16 + (lane & 7) + ((lane >> 4) & 1) * 8) * AT_LDB
                                + (uint32_t)((lane >> 3) & 1) * 16;
#pragma unroll
            for (int ks = 0; ks < 4; ks++) {
                uint32_t h0, h1, h2, h3, l0, l1, l2, l3;
                ldsm4(h0, h1, h2, h3, kb + brow + ks * 32);
                ldsm4(l0, l1, l2, l3, kb + AT_KSZ + brow + ks * 32);
                mma16816(sfr[2*nb],   qh[ks][0], qh[ks][1], qh[ks][2], qh[ks][3], h0, h1);
                mma16816(sfr[2*nb],   qh[ks][0], qh[ks][1], qh[ks][2], qh[ks][3], l0, l1);
                mma16816(sfr[2*nb],   ql[ks][0], ql[ks][1], ql[ks][2], ql[ks][3], h0, h1);
                mma16816(sfr[2*nb+1], qh[ks][0], qh[ks][1], qh[ks][2], qh[ks][3], h2, h3);
                mma16816(sfr[2*nb+1], qh[ks][0], qh[ks][1], qh[ks][2], qh[ks][3], l2, l3);
                mma16816(sfr[2*nb+1], ql[ks][0], ql[ks][1], ql[ks][2], ql[ks][3], h2, h3);
            }
        }

        // ---- causal mask (diagonal-overlapping tiles only) ----
        if (kt >= 2 * bq) {
            const int c0 = kt * 64 + (lane & 3) * 2;
#pragma unroll
            for (int j = 0; j < 8; j++) {
                const int c = c0 + j * 8;
                if (c     > rg)     sfr[j][0] = -1e30f;
                if (c + 1 > rg)     sfr[j][1] = -1e30f;
                if (c     > rg + 8) sfr[j][2] = -1e30f;
                if (c + 1 > rg + 8) sfr[j][3] = -1e30f;
            }
        }

        // ---- online softmax (2 rows per thread, quad shfl reduce) ----
#pragma unroll
        for (int r = 0; r < 2; r++) {
            float mx = -1e30f;
#pragma unroll
            for (int j = 0; j < 8; j++)
                mx = fmaxf(mx, fmaxf(sfr[j][2*r], sfr[j][2*r+1]));
            mx = fmaxf(mx, __shfl_xor_sync(0xffffffffu, mx, 1));
            mx = fmaxf(mx, __shfl_xor_sync(0xffffffffu, mx, 2));
            const float mnew = fmaxf(mrow[r], mx);
            const float corr = __expf(mrow[r] - mnew);
            mrow[r] = mnew;
            float sum = 0.f;
#pragma unroll
            for (int j = 0; j < 8; j++) {
                sfr[j][2*r]   = __expf(sfr[j][2*r]   - mnew);
                sfr[j][2*r+1] = __expf(sfr[j][2*r+1] - mnew);
                sum += sfr[j][2*r] + sfr[j][2*r+1];
            }
            sum += __shfl_xor_sync(0xffffffffu, sum, 1);
            sum += __shfl_xor_sync(0xffffffffu, sum, 2);
            lrow[r] = lrow[r] * corr + sum;
#pragma unroll
            for (int j = 0; j < 8; j++) {
                oacc[j][2*r]   *= corr;
                oacc[j][2*r+1] *= corr;
            }
        }

        // ---- pack P -> bf16 hi/lo a-frags (C-frag layout == A-frag layout) ----
        uint32_t ph[4][4], pl[4][4];
#pragma unroll
        for (int ks = 0; ks < 4; ks++) {
#pragma unroll
            for (int idx = 0; idx < 4; idx++) {
                const float a = sfr[2*ks + (idx >> 1)][(idx & 1) * 2];
                const float b = sfr[2*ks + (idx >> 1)][(idx & 1) * 2 + 1];
                __nv_bfloat16 ahB, alB, bhB, blB;
                split_bf16(a, ahB, alB);
                split_bf16(b, bhB, blB);
                ph[ks][idx] = pack2(ahB, bhB);
                pl[ks][idx] = pack2(alB, blB);
            }
        }

        // ---- O += P V (bf16x3, V via ldmatrix.trans) ----
        const uint32_t vb = kb + 2 * AT_KSZ;
#pragma unroll
        for (int ks = 0; ks < 4; ks++) {
            const uint32_t vrow = (uint32_t)(ks * 16 + (lane & 15)) * AT_LDB
                                + (uint32_t)(lane >> 4) * 16;
#pragma unroll
            for (int nb = 0; nb < 4; nb++) {
                uint32_t h0, h1, h2, h3, l0, l1, l2, l3;
                ldsm4t(h0, h1, h2, h3, vb + vrow + nb * 32);
                ldsm4t(l0, l1, l2, l3, vb + AT_KSZ + vrow + nb * 32);
                mma16816(oacc[2*nb],   ph[ks][0], ph[ks][1], ph[ks][2], ph[ks][3], h0, h1);
                mma16816(oacc[2*nb],   ph[ks][0], ph[ks][1], ph[ks][2], ph[ks][3], l0, l1);
                mma16816(oacc[2*nb],   pl[ks][0], pl[ks][1], pl[ks][2], pl[ks][3], h0, h1);
                mma16816(oacc[2*nb+1], ph[ks][0], ph[ks][1], ph[ks][2], ph[ks][3], h2, h3);
                mma16816(oacc[2*nb+1], ph[ks][0], ph[ks][1], ph[ks][2], ph[ks][3], l2, l3);
                mma16816(oacc[2*nb+1], pl[ks][0], pl[ks][1], pl[ks][2], pl[ks][3], h2, h3);
            }
        }

        __syncthreads();
        if (kt + 2 <= ktmax) LOAD_KV(kt + 2, kt & 1);
        CP_COMMIT();
    }

    // ---- epilogue: O/l -> bf16 hi/lo [m][k] for oproj ----
    const int b = bh >> 4, h = bh & 15;
    const float inv0 = 1.0f / lrow[0];
    const float inv1 = 1.0f / lrow[1];
#pragma unroll
    for (int j = 0; j < 8; j++) {
        const int e = j * 8 + (lane & 3) * 2;
#pragma unroll
        for (int r = 0; r < 2; r++) {
            const float inv = r ? inv1 : inv0;
            const float vx = oacc[j][2*r]     * inv;
            const float vy = oacc[j][2*r + 1] * inv;
            __nv_bfloat16 hx, lx, hy, ly;
            split_bf16(vx, hx, lx);
            split_bf16(vy, hy, ly);
            const size_t off = (size_t)(b * S_ + rg + r * 8) * KDIM + h * 64 + e;
            *(uint32_t*)(g_aohi + off) = pack2(hx, hy);
            *(uint32_t*)(g_aolo + off) = pack2(lx, ly);
        }
    }
#undef LOAD_KV
}

// ---------------------------------------------------------------------------
extern "C" void kernel_launch(void* const* d_in, const int* in_sizes, int n_in,
                              void* d_out, int out_size) {
    const float* x  = (const float*)d_in[0];
    const float* Wq = (const float*)d_in[1];
    const float* Wk = (const float*)d_in[2];
    const float* Wv = (const float*)d_in[3];
    const float* Wo = (const float*)d_in[4];
    const float* bo = (const float*)d_in[5];
    float* out = (float*)d_out;

    cudaFuncSetAttribute(gemm_mma, cudaFuncAttributeMaxDynamicSharedMemorySize,
                         (int)GEMM_SMEM);
    cudaFuncSetAttribute(attn_mma, cudaFuncAttributeMaxDynamicSharedMemorySize,
                         (int)AT_SMEM);

    conv_x_kernel<<<(M_TOT * KDIM) / (256 * 4), 256>>>(x);
    conv_wqkv_kernel<<<dim3(16, 16, 3), 256>>>(Wq, Wk, Wv);
    conv_wo_kernel<<<(D_ * KDIM) / (256 * 4), 256>>>(Wo);

    gemm_mma<<<dim3(NQKV / 128, M_TOT / 128), 256, GEMM_SMEM>>>(nullptr, nullptr, 0);
    attn_mma<<<dim3(S_ / 128, B_ * H_), 256, AT_SMEM>>>();
    gemm_mma<<<dim3(D_ / 128, M_TOT / 128), 256, GEMM_SMEM>>>(out, bo, 1);
}

// round 6
// speedup vs baseline: 2.7904x; 1.0449x over previous
#include <cuda_runtime.h>
#include <cuda_bf16.h>
#include <cstdint>

#define B_  4
#define S_  2048
#define D_  1024
#define H_  16
#define HD_ 64
#define M_TOT (B_*S_)     // 8192
#define NQKV  3072
#define KDIM  1024

// ---------------------------------------------------------------------------
// Device scratch (all bf16 hi/lo pairs)
// ---------------------------------------------------------------------------
__device__ __nv_bfloat16 g_xhi[(size_t)M_TOT*KDIM];
__device__ __nv_bfloat16 g_xlo[(size_t)M_TOT*KDIM];
__device__ __nv_bfloat16 g_wqkv_hi[(size_t)NQKV*KDIM];   // [n][k] K-major
__device__ __nv_bfloat16 g_wqkv_lo[(size_t)NQKV*KDIM];
__device__ __nv_bfloat16 g_wo_hi[(size_t)D_*KDIM];
__device__ __nv_bfloat16 g_wo_lo[(size_t)D_*KDIM];
__device__ __nv_bfloat16 g_qhi[(size_t)B_*H_*S_*HD_];    // [b,h,s,e], Q pre-scaled
__device__ __nv_bfloat16 g_qlo[(size_t)B_*H_*S_*HD_];
__device__ __nv_bfloat16 g_khi[(size_t)B_*H_*S_*HD_];
__device__ __nv_bfloat16 g_klo[(size_t)B_*H_*S_*HD_];
__device__ __nv_bfloat16 g_vhi[(size_t)B_*H_*S_*HD_];
__device__ __nv_bfloat16 g_vlo[(size_t)B_*H_*S_*HD_];
__device__ __nv_bfloat16 g_aohi[(size_t)M_TOT*KDIM];     // attention out [m][k]
__device__ __nv_bfloat16 g_aolo[(size_t)M_TOT*KDIM];

// ---------------------------------------------------------------------------
// Portable PTX helpers (sm_80+ ISA only)
// ---------------------------------------------------------------------------
__device__ __forceinline__ uint32_t smem_u32(const void* p) {
    uint32_t a;
    asm("{ .reg .u64 t; cvta.to.shared.u64 t, %1; cvt.u32.u64 %0, t; }"
        : "=r"(a) : "l"(p));
    return a;
}

__device__ __forceinline__ void cp16(uint32_t dst, const void* src) {
    asm volatile("cp.async.cg.shared.global [%0], [%1], 16;"
                 :: "r"(dst), "l"(src) : "memory");
}
#define CP_COMMIT() asm volatile("cp.async.commit_group;" ::: "memory")
#define CP_WAIT2()  asm volatile("cp.async.wait_group 2;"  ::: "memory")
#define CP_WAIT1()  asm volatile("cp.async.wait_group 1;"  ::: "memory")

__device__ __forceinline__ void ldsm4(uint32_t& r0, uint32_t& r1,
                                      uint32_t& r2, uint32_t& r3, uint32_t addr) {
    asm volatile("ldmatrix.sync.aligned.m8n8.x4.shared.b16 {%0,%1,%2,%3}, [%4];"
                 : "=r"(r0), "=r"(r1), "=r"(r2), "=r"(r3) : "r"(addr));
}
__device__ __forceinline__ void ldsm4t(uint32_t& r0, uint32_t& r1,
                                       uint32_t& r2, uint32_t& r3, uint32_t addr) {
    asm volatile("ldmatrix.sync.aligned.m8n8.x4.trans.shared.b16 {%0,%1,%2,%3}, [%4];"
                 : "=r"(r0), "=r"(r1), "=r"(r2), "=r"(r3) : "r"(addr));
}

__device__ __forceinline__ void mma16816(float* c,
                                         uint32_t a0, uint32_t a1, uint32_t a2, uint32_t a3,
                                         uint32_t b0, uint32_t b1) {
    asm volatile(
        "mma.sync.aligned.m16n8k16.row.col.f32.bf16.bf16.f32 "
        "{%0,%1,%2,%3}, {%4,%5,%6,%7}, {%8,%9}, {%0,%1,%2,%3};"
        : "+f"(c[0]), "+f"(c[1]), "+f"(c[2]), "+f"(c[3])
        : "r"(a0), "r"(a1), "r"(a2), "r"(a3), "r"(b0), "r"(b1));
}

__device__ __forceinline__ void split_bf16(float v, __nv_bfloat16& hi, __nv_bfloat16& lo) {
    hi = __float2bfloat16(v);
    lo = __float2bfloat16(v - __bfloat162float(hi));
}
__device__ __forceinline__ uint32_t pack2(__nv_bfloat16 a, __nv_bfloat16 b) {
    __nv_bfloat162 t; t.x = a; t.y = b;
    return *(uint32_t*)&t;
}

// ---------------------------------------------------------------------------
// Conversion kernels
// ---------------------------------------------------------------------------
__global__ void conv_x_kernel(const float* __restrict__ src) {
    size_t i = ((size_t)blockIdx.x * 256 + threadIdx.x) * 4;
    float4 v = *(const float4*)(src + i);
    __nv_bfloat16 h, l;
    split_bf16(v.x, h, l); g_xhi[i+0] = h; g_xlo[i+0] = l;
    split_bf16(v.y, h, l); g_xhi[i+1] = h; g_xlo[i+1] = l;
    split_bf16(v.z, h, l); g_xhi[i+2] = h; g_xlo[i+2] = l;
    split_bf16(v.w, h, l); g_xhi[i+3] = h; g_xlo[i+3] = l;
}

__global__ void conv_wo_kernel(const float* __restrict__ src) {
    size_t i = ((size_t)blockIdx.x * 256 + threadIdx.x) * 4;
    float4 v = *(const float4*)(src + i);
    __nv_bfloat16 h, l;
    split_bf16(v.x, h, l); g_wo_hi[i+0] = h; g_wo_lo[i+0] = l;
    split_bf16(v.y, h, l); g_wo_hi[i+1] = h; g_wo_lo[i+1] = l;
    split_bf16(v.z, h, l); g_wo_hi[i+2] = h; g_wo_lo[i+2] = l;
    split_bf16(v.w, h, l); g_wo_hi[i+3] = h; g_wo_lo[i+3] = l;
}

__global__ void conv_wqkv_kernel(const float* __restrict__ Wq,
                                 const float* __restrict__ Wk,
                                 const float* __restrict__ Wv) {
    __shared__ float t[64][65];
    const int p = blockIdx.z, h = blockIdx.y, d0 = blockIdx.x * 64;
    const float* W = (p == 0) ? Wq : ((p == 1) ? Wk : Wv);
    const float* Wh = W + (size_t)h * D_ * HD_;
    const int tid = threadIdx.x;
#pragma unroll
    for (int j = 0; j < 16; j++) {
        int idx = tid + j * 256;
        int d = idx >> 6, e = idx & 63;
        t[d][e] = Wh[(size_t)(d0 + d) * HD_ + e];
    }
    __syncthreads();
#pragma unroll
    for (int j = 0; j < 16; j++) {
        int idx = tid + j * 256;
        int e = idx >> 6, d = idx & 63;
        float v = t[d][e];
        __nv_bfloat16 hi, lo;
        split_bf16(v, hi, lo);
        size_t out = (size_t)(p * 1024 + h * 64 + e) * KDIM + d0 + d;
        g_wqkv_hi[out] = hi;
        g_wqkv_lo[out] = lo;
    }
}

// ---------------------------------------------------------------------------
// bf16x3 GEMM via mma.sync.m16n8k16.
// R6: 512 threads, 16 warps (4x4), warp tile 32x32 -> 4 warps/SMSP to cover
// ldsm/MMA/barrier latency. Same 4-stage cp.async pipeline.
// mode 0: x @ wqkv -> bf16 hi/lo Q(scaled)/K/V ; mode 1: ao @ wo -> out+bias
// ---------------------------------------------------------------------------
#define ARR_B     10240           // 128 rows x 80B (32 bf16 + 16B pad)
#define STAGE_B   (4 * ARR_B)     // Ahi, Alo, Bhi, Blo
#define GEMM_SMEM (4 * STAGE_B)   // 163840

__global__ __launch_bounds__(512)
void gemm_mma(float* __restrict__ outp, const float* __restrict__ bias, int mode) {
    extern __shared__ __align__(128) char smem[];
    const uint32_t sb = smem_u32(smem);
    const int tid = threadIdx.x;
    const int warp = tid >> 5, lane = tid & 31;
    const int wm = warp >> 2, wn = warp & 3;     // 4x4 warp grid, 32x32 tiles
    const int m0 = blockIdx.y * 128, n0 = blockIdx.x * 128;

    const __nv_bfloat16* Ahi = mode ? g_aohi : g_xhi;
    const __nv_bfloat16* Alo = mode ? g_aolo : g_xlo;
    const __nv_bfloat16* Bhi = mode ? g_wo_hi : g_wqkv_hi;
    const __nv_bfloat16* Blo = mode ? g_wo_lo : g_wqkv_lo;

    // loader: 1 cp16 per array per stage (512 threads x 1 = 512 chunks = 128rows x 4)
    const int lr = tid >> 2;            // 0..127
    const int lc = tid & 3;             // 16B chunk
    const size_t gA = (size_t)(m0 + lr) * KDIM + lc * 8;
    const size_t gB = (size_t)(n0 + lr) * KDIM + lc * 8;
    const uint32_t so = (uint32_t)lr * 80 + (uint32_t)lc * 16;

#define LOAD_STAGE(st, kel) do { \
    uint32_t b_ = sb + (uint32_t)(st) * STAGE_B; \
    cp16(b_ +             so, Ahi + gA + (kel)); \
    cp16(b_ +     ARR_B + so, Alo + gA + (kel)); \
    cp16(b_ + 2 * ARR_B + so, Bhi + gB + (kel)); \
    cp16(b_ + 3 * ARR_B + so, Blo + gB + (kel)); \
} while (0)

    LOAD_STAGE(0, 0);  CP_COMMIT();
    LOAD_STAGE(1, 32); CP_COMMIT();
    LOAD_STAGE(2, 64); CP_COMMIT();

    const uint32_t aoff = (uint32_t)(wm * 32 + (lane & 15)) * 80 + (uint32_t)(lane >> 4) * 16;
    const uint32_t boff = (uint32_t)(wn * 32 + (lane & 7) + ((lane >> 4) & 1) * 8) * 80
                        + (uint32_t)((lane >> 3) & 1) * 16;

    float c[2][4][4];
#pragma unroll
    for (int i = 0; i < 2; i++)
#pragma unroll
        for (int j = 0; j < 4; j++)
#pragma unroll
            for (int r = 0; r < 4; r++) c[i][j][r] = 0.f;

    for (int ck = 0; ck < 32; ck++) {
        CP_WAIT2();
        __syncthreads();
        const uint32_t base = sb + (uint32_t)(ck & 3) * STAGE_B;
        if (ck + 3 < 32) LOAD_STAGE((ck + 3) & 3, (size_t)(ck + 3) * 32);
        CP_COMMIT();

#pragma unroll
        for (int kk = 0; kk < 2; kk++) {
            uint32_t ah[2][4], al[2][4], bh[4][2], bl[4][2];
#pragma unroll
            for (int i = 0; i < 2; i++) {
                ldsm4(ah[i][0], ah[i][1], ah[i][2], ah[i][3],
                      base + aoff + i * 1280 + kk * 32);
                ldsm4(al[i][0], al[i][1], al[i][2], al[i][3],
                      base + ARR_B + aoff + i * 1280 + kk * 32);
            }
#pragma unroll
            for (int p = 0; p < 2; p++) {
                uint32_t r0, r1, r2, r3;
                ldsm4(r0, r1, r2, r3, base + 2 * ARR_B + boff + p * 1280 + kk * 32);
                bh[2*p][0] = r0; bh[2*p][1] = r1; bh[2*p+1][0] = r2; bh[2*p+1][1] = r3;
                ldsm4(r0, r1, r2, r3, base + 3 * ARR_B + boff + p * 1280 + kk * 32);
                bl[2*p][0] = r0; bl[2*p][1] = r1; bl[2*p+1][0] = r2; bl[2*p+1][1] = r3;
            }
#pragma unroll
            for (int i = 0; i < 2; i++)
#pragma unroll
                for (int j = 0; j < 4; j++) {
                    mma16816(c[i][j], ah[i][0], ah[i][1], ah[i][2], ah[i][3],
                             bh[j][0], bh[j][1]);
                    mma16816(c[i][j], ah[i][0], ah[i][1], ah[i][2], ah[i][3],
                             bl[j][0], bl[j][1]);
                    mma16816(c[i][j], al[i][0], al[i][1], al[i][2], al[i][3],
                             bh[j][0], bh[j][1]);
                }
        }
    }

#pragma unroll
    for (int i = 0; i < 2; i++) {
#pragma unroll
        for (int j = 0; j < 4; j++) {
            const int ncol = n0 + wn * 32 + j * 8 + (lane & 3) * 2;
#pragma unroll
            for (int half = 0; half < 2; half++) {
                const int row = m0 + wm * 32 + i * 16 + (lane >> 2) + half * 8;
                float vx = c[i][j][half * 2], vy = c[i][j][half * 2 + 1];
                if (mode == 0) {
                    const int p = ncol >> 10;
                    const float sc = (p == 0) ? 0.125f : 1.0f;
                    __nv_bfloat16* Th = (p == 0) ? g_qhi : ((p == 1) ? g_khi : g_vhi);
                    __nv_bfloat16* Tl = (p == 0) ? g_qlo : ((p == 1) ? g_klo : g_vlo);
                    const int h = (ncol & 1023) >> 6;
                    const int e = ncol & 63;
                    const int bb = row >> 11, ss = row & 2047;
                    __nv_bfloat16 hx, lx, hy, ly;
                    split_bf16(vx * sc, hx, lx);
                    split_bf16(vy * sc, hy, ly);
                    const size_t off = ((size_t)(bb * H_ + h) * S_ + ss) * HD_ + e;
                    *(uint32_t*)(Th + off) = pack2(hx, hy);
                    *(uint32_t*)(Tl + off) = pack2(lx, ly);
                } else {
                    float2 bv = *(const float2*)(bias + ncol);
                    float2 v = make_float2(vx + bv.x, vy + bv.y);
                    *(float2*)(outp + (size_t)row * D_ + ncol) = v;
                }
            }
        }
    }
#undef LOAD_STAGE
}

// ---------------------------------------------------------------------------
// Tensor-core causal flash attention (R5-verified, unchanged).
// ---------------------------------------------------------------------------
#define AT_LDB  144
#define AT_KSZ  (64 * AT_LDB)
#define AT_STAGE (4 * AT_KSZ)
#define AT_Q    (2 * 128 * AT_LDB)
#define AT_SMEM (AT_Q + 2 * AT_STAGE)

__global__ __launch_bounds__(256, 1)
void attn_mma() {
    extern __shared__ __align__(128) char smc[];
    const uint32_t sb = smem_u32(smc);
    const int tid = threadIdx.x;
    const int warp = tid >> 5, lane = tid & 31;
    const int bq = blockIdx.x, bh = blockIdx.y;
    const int q0 = bq * 128;

    const __nv_bfloat16* Qh = g_qhi + (size_t)bh * S_ * HD_;
    const __nv_bfloat16* Ql = g_qlo + (size_t)bh * S_ * HD_;
    const __nv_bfloat16* Kh = g_khi + (size_t)bh * S_ * HD_;
    const __nv_bfloat16* Kl = g_klo + (size_t)bh * S_ * HD_;
    const __nv_bfloat16* Vh = g_vhi + (size_t)bh * S_ * HD_;
    const __nv_bfloat16* Vl = g_vlo + (size_t)bh * S_ * HD_;

#pragma unroll
    for (int i = 0; i < 4; i++) {
        int idx = tid + i * 256;
        int r = idx >> 3, ch = idx & 7;
        size_t g = (size_t)(q0 + r) * HD_ + ch * 8;
        cp16(sb + r * AT_LDB + ch * 16, Qh + g);
        cp16(sb + 128 * AT_LDB + r * AT_LDB + ch * 16, Ql + g);
    }
    CP_COMMIT();

    const int ktmax = 2 * bq + 1;

#define LOAD_KV(kt, st) do { \
    uint32_t kb_ = sb + AT_Q + (uint32_t)(st) * AT_STAGE; \
    int t0_ = (kt) * 64; \
    _Pragma("unroll") \
    for (int i_ = 0; i_ < 2; i_++) { \
        int idx_ = tid + i_ * 256; \
        int r_ = idx_ >> 3, ch_ = idx_ & 7; \
        size_t g_ = (size_t)(t0_ + r_) * HD_ + ch_ * 8; \
        uint32_t s_ = (uint32_t)r_ * AT_LDB + (uint32_t)ch_ * 16; \
        cp16(kb_ + s_,              Kh + g_); \
        cp16(kb_ +     AT_KSZ + s_, Kl + g_); \
        cp16(kb_ + 2 * AT_KSZ + s_, Vh + g_); \
        cp16(kb_ + 3 * AT_KSZ + s_, Vl + g_); \
    } } while (0)

    LOAD_KV(0, 0); CP_COMMIT();
    CP_WAIT1();
    __syncthreads();

    uint32_t qh[4][4], ql[4][4];
    const uint32_t aoff = (uint32_t)(warp * 16 + (lane & 15)) * AT_LDB
                        + (uint32_t)(lane >> 4) * 16;
#pragma unroll
    for (int ks = 0; ks < 4; ks++) {
        ldsm4(qh[ks][0], qh[ks][1], qh[ks][2], qh[ks][3], sb + aoff + ks * 32);
        ldsm4(ql[ks][0], ql[ks][1], ql[ks][2], ql[ks][3],
              sb + 128 * AT_LDB + aoff + ks * 32);
    }
    if (1 <= ktmax) LOAD_KV(1, 1);
    CP_COMMIT();

    float oacc[8][4];
#pragma unroll
    for (int j = 0; j < 8; j++)
#pragma unroll
        for (int r = 0; r < 4; r++) oacc[j][r] = 0.f;
    float mrow[2] = {-1e30f, -1e30f};
    float lrow[2] = {0.f, 0.f};

    const int rg = q0 + warp * 16 + (lane >> 2);

    for (int kt = 0; kt <= ktmax; kt++) {
        CP_WAIT1();
        __syncthreads();
        const uint32_t kb = sb + AT_Q + (uint32_t)(kt & 1) * AT_STAGE;

        float sfr[8][4];
#pragma unroll
        for (int j = 0; j < 8; j++)
#pragma unroll
            for (int r = 0; r < 4; r++) sfr[j][r] = 0.f;

#pragma unroll
        for (int nb = 0; nb < 4; nb++) {
            const uint32_t brow = (uint32_t)(nb * 16 + (lane & 7) + ((lane >> 4) & 1) * 8) * AT_LDB
                                + (uint32_t)((lane >> 3) & 1) * 16;
#pragma unroll
            for (int ks = 0; ks < 4; ks++) {
                uint32_t h0, h1, h2, h3, l0, l1, l2, l3;
                ldsm4(h0, h1, h2, h3, kb + brow + ks * 32);
                ldsm4(l0, l1, l2, l3, kb + AT_KSZ + brow + ks * 32);
                mma16816(sfr[2*nb],   qh[ks][0], qh[ks][1], qh[ks][2], qh[ks][3], h0, h1);
                mma16816(sfr[2*nb],   qh[ks][0], qh[ks][1], qh[ks][2], qh[ks][3], l0, l1);
                mma16816(sfr[2*nb],   ql[ks][0], ql[ks][1], ql[ks][2], ql[ks][3], h0, h1);
                mma16816(sfr[2*nb+1], qh[ks][0], qh[ks][1], qh[ks][2], qh[ks][3], h2, h3);
                mma16816(sfr[2*nb+1], qh[ks][0], qh[ks][1], qh[ks][2], qh[ks][3], l2, l3);
                mma16816(sfr[2*nb+1], ql[ks][0], ql[ks][1], ql[ks][2], ql[ks][3], h2, h3);
            }
        }

        if (kt >= 2 * bq) {
            const int c0 = kt * 64 + (lane & 3) * 2;
#pragma unroll
            for (int j = 0; j < 8; j++) {
                const int c = c0 + j * 8;
                if (c     > rg)     sfr[j][0] = -1e30f;
                if (c + 1 > rg)     sfr[j][1] = -1e30f;
                if (c     > rg + 8) sfr[j][2] = -1e30f;
                if (c + 1 > rg + 8) sfr[j][3] = -1e30f;
            }
        }

#pragma unroll
        for (int r = 0; r < 2; r++) {
            float mx = -1e30f;
#pragma unroll
            for (int j = 0; j < 8; j++)
                mx = fmaxf(mx, fmaxf(sfr[j][2*r], sfr[j][2*r+1]));
            mx = fmaxf(mx, __shfl_xor_sync(0xffffffffu, mx, 1));
            mx = fmaxf(mx, __shfl_xor_sync(0xffffffffu, mx, 2));
            const float mnew = fmaxf(mrow[r], mx);
            const float corr = __expf(mrow[r] - mnew);
            mrow[r] = mnew;
            float sum = 0.f;
#pragma unroll
            for (int j = 0; j < 8; j++) {
                sfr[j][2*r]   = __expf(sfr[j][2*r]   - mnew);
                sfr[j][2*r+1] = __expf(sfr[j][2*r+1] - mnew);
                sum += sfr[j][2*r] + sfr[j][2*r+1];
            }
            sum += __shfl_xor_sync(0xffffffffu, sum, 1);
            sum += __shfl_xor_sync(0xffffffffu, sum, 2);
            lrow[r] = lrow[r] * corr + sum;
#pragma unroll
            for (int j = 0; j < 8; j++) {
                oacc[j][2*r]   *= corr;
                oacc[j][2*r+1] *= corr;
            }
        }

        uint32_t ph[4][4], pl[4][4];
#pragma unroll
        for (int ks = 0; ks < 4; ks++) {
#pragma unroll
            for (int idx = 0; idx < 4; idx++) {
                const float a = sfr[2*ks + (idx >> 1)][(idx & 1) * 2];
                const float b = sfr[2*ks + (idx >> 1)][(idx & 1) * 2 + 1];
                __nv_bfloat16 ahB, alB, bhB, blB;
                split_bf16(a, ahB, alB);
                split_bf16(b, bhB, blB);
                ph[ks][idx] = pack2(ahB, bhB);
                pl[ks][idx] = pack2(alB, blB);
            }
        }

        const uint32_t vb = kb + 2 * AT_KSZ;
#pragma unroll
        for (int ks = 0; ks < 4; ks++) {
            const uint32_t vrow = (uint32_t)(ks * 16 + (lane & 15)) * AT_LDB
                                + (uint32_t)(lane >> 4) * 16;
#pragma unroll
            for (int nb = 0; nb < 4; nb++) {
                uint32_t h0, h1, h2, h3, l0, l1, l2, l3;
                ldsm4t(h0, h1, h2, h3, vb + vrow + nb * 32);
                ldsm4t(l0, l1, l2, l3, vb + AT_KSZ + vrow + nb * 32);
                mma16816(oacc[2*nb],   ph[ks][0], ph[ks][1], ph[ks][2], ph[ks][3], h0, h1);
                mma16816(oacc[2*nb],   ph[ks][0], ph[ks][1], ph[ks][2], ph[ks][3], l0, l1);
                mma16816(oacc[2*nb],   pl[ks][0], pl[ks][1], pl[ks][2], pl[ks][3], h0, h1);
                mma16816(oacc[2*nb+1], ph[ks][0], ph[ks][1], ph[ks][2], ph[ks][3], h2, h3);
                mma16816(oacc[2*nb+1], ph[ks][0], ph[ks][1], ph[ks][2], ph[ks][3], l2, l3);
                mma16816(oacc[2*nb+1], pl[ks][0], pl[ks][1], pl[ks][2], pl[ks][3], h2, h3);
            }
        }

        __syncthreads();
        if (kt + 2 <= ktmax) LOAD_KV(kt + 2, kt & 1);
        CP_COMMIT();
    }

    const int b = bh >> 4, h = bh & 15;
    const float inv0 = 1.0f / lrow[0];
    const float inv1 = 1.0f / lrow[1];
#pragma unroll
    for (int j = 0; j < 8; j++) {
        const int e = j * 8 + (lane & 3) * 2;
#pragma unroll
        for (int r = 0; r < 2; r++) {
            const float inv = r ? inv1 : inv0;
            const float vx = oacc[j][2*r]     * inv;
            const float vy = oacc[j][2*r + 1] * inv;
            __nv_bfloat16 hx, lx, hy, ly;
            split_bf16(vx, hx, lx);
            split_bf16(vy, hy, ly);
            const size_t off = (size_t)(b * S_ + rg + r * 8) * KDIM + h * 64 + e;
            *(uint32_t*)(g_aohi + off) = pack2(hx, hy);
            *(uint32_t*)(g_aolo + off) = pack2(lx, ly);
        }
    }
#undef LOAD_KV
}

// ---------------------------------------------------------------------------
extern "C" void kernel_launch(void* const* d_in, const int* in_sizes, int n_in,
                              void* d_out, int out_size) {
    const float* x  = (const float*)d_in[0];
    const float* Wq = (const float*)d_in[1];
    const float* Wk = (const float*)d_in[2];
    const float* Wv = (const float*)d_in[3];
    const float* Wo = (const float*)d_in[4];
    const float* bo = (const float*)d_in[5];
    float* out = (float*)d_out;

    cudaFuncSetAttribute(gemm_mma, cudaFuncAttributeMaxDynamicSharedMemorySize,
                         (int)GEMM_SMEM);
    cudaFuncSetAttribute(attn_mma, cudaFuncAttributeMaxDynamicSharedMemorySize,
                         (int)AT_SMEM);

    conv_x_kernel<<<(M_TOT * KDIM) / (256 * 4), 256>>>(x);
    conv_wqkv_kernel<<<dim3(16, 16, 3), 256>>>(Wq, Wk, Wv);
    conv_wo_kernel<<<(D_ * KDIM) / (256 * 4), 256>>>(Wo);

    gemm_mma<<<dim3(NQKV / 128, M_TOT / 128), 512, GEMM_SMEM>>>(nullptr, nullptr, 0);
    attn_mma<<<dim3(S_ / 128, B_ * H_), 256, AT_SMEM>>>();
    gemm_mma<<<dim3(D_ / 128, M_TOT / 128), 512, GEMM_SMEM>>>(out, bo, 1);
}

// round 7
// speedup vs baseline: 2.8715x; 1.0291x over previous
#include <cuda_runtime.h>
#include <cuda_bf16.h>
#include <cstdint>

#define B_  4
#define S_  2048
#define D_  1024
#define H_  16
#define HD_ 64
#define M_TOT (B_*S_)     // 8192
#define NQKV  3072
#define KDIM  1024

// ---------------------------------------------------------------------------
// Device scratch (all bf16 hi/lo pairs)
// ---------------------------------------------------------------------------
__device__ __nv_bfloat16 g_xhi[(size_t)M_TOT*KDIM];
__device__ __nv_bfloat16 g_xlo[(size_t)M_TOT*KDIM];
__device__ __nv_bfloat16 g_wqkv_hi[(size_t)NQKV*KDIM];   // [n][k] K-major
__device__ __nv_bfloat16 g_wqkv_lo[(size_t)NQKV*KDIM];
__device__ __nv_bfloat16 g_wo_hi[(size_t)D_*KDIM];
__device__ __nv_bfloat16 g_wo_lo[(size_t)D_*KDIM];
__device__ __nv_bfloat16 g_qhi[(size_t)B_*H_*S_*HD_];    // [b,h,s,e], Q pre-scaled
__device__ __nv_bfloat16 g_qlo[(size_t)B_*H_*S_*HD_];
__device__ __nv_bfloat16 g_khi[(size_t)B_*H_*S_*HD_];
__device__ __nv_bfloat16 g_klo[(size_t)B_*H_*S_*HD_];
__device__ __nv_bfloat16 g_vhi[(size_t)B_*H_*S_*HD_];
__device__ __nv_bfloat16 g_vlo[(size_t)B_*H_*S_*HD_];
__device__ __nv_bfloat16 g_aohi[(size_t)M_TOT*KDIM];     // attention out [m][k]
__device__ __nv_bfloat16 g_aolo[(size_t)M_TOT*KDIM];

// ---------------------------------------------------------------------------
// Portable PTX helpers (sm_80+ ISA only)
// ---------------------------------------------------------------------------
__device__ __forceinline__ uint32_t smem_u32(const void* p) {
    uint32_t a;
    asm("{ .reg .u64 t; cvta.to.shared.u64 t, %1; cvt.u32.u64 %0, t; }"
        : "=r"(a) : "l"(p));
    return a;
}

__device__ __forceinline__ void cp16(uint32_t dst, const void* src) {
    asm volatile("cp.async.cg.shared.global [%0], [%1], 16;"
                 :: "r"(dst), "l"(src) : "memory");
}
#define CP_COMMIT() asm volatile("cp.async.commit_group;" ::: "memory")
#define CP_WAIT1()  asm volatile("cp.async.wait_group 1;"  ::: "memory")

__device__ __forceinline__ void ldsm4(uint32_t& r0, uint32_t& r1,
                                      uint32_t& r2, uint32_t& r3, uint32_t addr) {
    asm volatile("ldmatrix.sync.aligned.m8n8.x4.shared.b16 {%0,%1,%2,%3}, [%4];"
                 : "=r"(r0), "=r"(r1), "=r"(r2), "=r"(r3) : "r"(addr));
}
__device__ __forceinline__ void ldsm4t(uint32_t& r0, uint32_t& r1,
                                       uint32_t& r2, uint32_t& r3, uint32_t addr) {
    asm volatile("ldmatrix.sync.aligned.m8n8.x4.trans.shared.b16 {%0,%1,%2,%3}, [%4];"
                 : "=r"(r0), "=r"(r1), "=r"(r2), "=r"(r3) : "r"(addr));
}

__device__ __forceinline__ void mma16816(float* c,
                                         uint32_t a0, uint32_t a1, uint32_t a2, uint32_t a3,
                                         uint32_t b0, uint32_t b1) {
    asm volatile(
        "mma.sync.aligned.m16n8k16.row.col.f32.bf16.bf16.f32 "
        "{%0,%1,%2,%3}, {%4,%5,%6,%7}, {%8,%9}, {%0,%1,%2,%3};"
        : "+f"(c[0]), "+f"(c[1]), "+f"(c[2]), "+f"(c[3])
        : "r"(a0), "r"(a1), "r"(a2), "r"(a3), "r"(b0), "r"(b1));
}

__device__ __forceinline__ void split_bf16(float v, __nv_bfloat16& hi, __nv_bfloat16& lo) {
    hi = __float2bfloat16(v);
    lo = __float2bfloat16(v - __bfloat162float(hi));
}
__device__ __forceinline__ uint32_t pack2(__nv_bfloat16 a, __nv_bfloat16 b) {
    __nv_bfloat162 t; t.x = a; t.y = b;
    return *(uint32_t*)&t;
}

// ---------------------------------------------------------------------------
// Conversion kernels
// ---------------------------------------------------------------------------
__global__ void conv_x_kernel(const float* __restrict__ src) {
    size_t i = ((size_t)blockIdx.x * 256 + threadIdx.x) * 4;
    float4 v = *(const float4*)(src + i);
    __nv_bfloat16 h, l;
    split_bf16(v.x, h, l); g_xhi[i+0] = h; g_xlo[i+0] = l;
    split_bf16(v.y, h, l); g_xhi[i+1] = h; g_xlo[i+1] = l;
    split_bf16(v.z, h, l); g_xhi[i+2] = h; g_xlo[i+2] = l;
    split_bf16(v.w, h, l); g_xhi[i+3] = h; g_xlo[i+3] = l;
}

__global__ void conv_wo_kernel(const float* __restrict__ src) {
    size_t i = ((size_t)blockIdx.x * 256 + threadIdx.x) * 4;
    float4 v = *(const float4*)(src + i);
    __nv_bfloat16 h, l;
    split_bf16(v.x, h, l); g_wo_hi[i+0] = h; g_wo_lo[i+0] = l;
    split_bf16(v.y, h, l); g_wo_hi[i+1] = h; g_wo_lo[i+1] = l;
    split_bf16(v.z, h, l); g_wo_hi[i+2] = h; g_wo_lo[i+2] = l;
    split_bf16(v.w, h, l); g_wo_hi[i+3] = h; g_wo_lo[i+3] = l;
}

__global__ void conv_wqkv_kernel(const float* __restrict__ Wq,
                                 const float* __restrict__ Wk,
                                 const float* __restrict__ Wv) {
    __shared__ float t[64][65];
    const int p = blockIdx.z, h = blockIdx.y, d0 = blockIdx.x * 64;
    const float* W = (p == 0) ? Wq : ((p == 1) ? Wk : Wv);
    const float* Wh = W + (size_t)h * D_ * HD_;
    const int tid = threadIdx.x;
#pragma unroll
    for (int j = 0; j < 16; j++) {
        int idx = tid + j * 256;
        int d = idx >> 6, e = idx & 63;
        t[d][e] = Wh[(size_t)(d0 + d) * HD_ + e];
    }
    __syncthreads();
#pragma unroll
    for (int j = 0; j < 16; j++) {
        int idx = tid + j * 256;
        int e = idx >> 6, d = idx & 63;
        float v = t[d][e];
        __nv_bfloat16 hi, lo;
        split_bf16(v, hi, lo);
        size_t out = (size_t)(p * 1024 + h * 64 + e) * KDIM + d0 + d;
        g_wqkv_hi[out] = hi;
        g_wqkv_lo[out] = lo;
    }
}

// ---------------------------------------------------------------------------
// bf16x3 GEMM via mma.sync.m16n8k16.
// R7: BK=64, 16 chunks, 3-stage pipeline (221 KB smem) -> half the barriers,
// 2x MMA run-length per sync. 512 threads, 16 warps (4x4), warp tile 32x32.
// mode 0: x @ wqkv -> bf16 hi/lo Q(scaled)/K/V ; mode 1: ao @ wo -> out+bias
// ---------------------------------------------------------------------------
#define ARR_B     18432           // 128 rows x 144B (64 bf16 + 16B pad)
#define STAGE_B   (4 * ARR_B)     // Ahi, Alo, Bhi, Blo = 73728
#define GEMM_SMEM (3 * STAGE_B)   // 221184
#define NCHUNK    16              // K = 1024 / 64

__global__ __launch_bounds__(512)
void gemm_mma(float* __restrict__ outp, const float* __restrict__ bias, int mode) {
    extern __shared__ __align__(128) char smem[];
    const uint32_t sb = smem_u32(smem);
    const int tid = threadIdx.x;
    const int warp = tid >> 5, lane = tid & 31;
    const int wm = warp >> 2, wn = warp & 3;     // 4x4 warp grid, 32x32 tiles
    const int m0 = blockIdx.y * 128, n0 = blockIdx.x * 128;

    const __nv_bfloat16* Ahi = mode ? g_aohi : g_xhi;
    const __nv_bfloat16* Alo = mode ? g_aolo : g_xlo;
    const __nv_bfloat16* Bhi = mode ? g_wo_hi : g_wqkv_hi;
    const __nv_bfloat16* Blo = mode ? g_wo_lo : g_wqkv_lo;

    // loader: 128 rows x 8 chunks of 16B = 1024 slots per array; 2 per thread
    const int r0_ = tid >> 3, c0_ = tid & 7;           // slot 0
    const int r1_ = (tid + 512) >> 3, c1_ = tid & 7;   // slot 1 (rows 64..127)
    const size_t gA0 = (size_t)(m0 + r0_) * KDIM + c0_ * 8;
    const size_t gA1 = (size_t)(m0 + r1_) * KDIM + c1_ * 8;
    const size_t gB0 = (size_t)(n0 + r0_) * KDIM + c0_ * 8;
    const size_t gB1 = (size_t)(n0 + r1_) * KDIM + c1_ * 8;
    const uint32_t so0 = (uint32_t)r0_ * 144 + (uint32_t)c0_ * 16;
    const uint32_t so1 = (uint32_t)r1_ * 144 + (uint32_t)c1_ * 16;

#define LOAD_STAGE(st, kel) do { \
    uint32_t b_ = sb + (uint32_t)(st) * STAGE_B; \
    cp16(b_ +             so0, Ahi + gA0 + (kel)); \
    cp16(b_ +             so1, Ahi + gA1 + (kel)); \
    cp16(b_ +     ARR_B + so0, Alo + gA0 + (kel)); \
    cp16(b_ +     ARR_B + so1, Alo + gA1 + (kel)); \
    cp16(b_ + 2 * ARR_B + so0, Bhi + gB0 + (kel)); \
    cp16(b_ + 2 * ARR_B + so1, Bhi + gB1 + (kel)); \
    cp16(b_ + 3 * ARR_B + so0, Blo + gB0 + (kel)); \
    cp16(b_ + 3 * ARR_B + so1, Blo + gB1 + (kel)); \
} while (0)

    LOAD_STAGE(0, 0);  CP_COMMIT();
    LOAD_STAGE(1, 64); CP_COMMIT();

    const uint32_t aoff = (uint32_t)(wm * 32 + (lane & 15)) * 144 + (uint32_t)(lane >> 4) * 16;
    const uint32_t boff = (uint32_t)(wn * 32 + (lane & 7) + ((lane >> 4) & 1) * 8) * 144
                        + (uint32_t)((lane >> 3) & 1) * 16;

    float c[2][4][4];
#pragma unroll
    for (int i = 0; i < 2; i++)
#pragma unroll
        for (int j = 0; j < 4; j++)
#pragma unroll
            for (int r = 0; r < 4; r++) c[i][j][r] = 0.f;

    for (int ck = 0; ck < NCHUNK; ck++) {
        CP_WAIT1();
        __syncthreads();
        const uint32_t base = sb + (uint32_t)(ck % 3) * STAGE_B;
        if (ck + 2 < NCHUNK) LOAD_STAGE((ck + 2) % 3, (size_t)(ck + 2) * 64);
        CP_COMMIT();

#pragma unroll
        for (int kk = 0; kk < 4; kk++) {
            uint32_t ah[2][4], al[2][4], bh[4][2], bl[4][2];
#pragma unroll
            for (int i = 0; i < 2; i++) {
                ldsm4(ah[i][0], ah[i][1], ah[i][2], ah[i][3],
                      base + aoff + i * 2304 + kk * 32);
                ldsm4(al[i][0], al[i][1], al[i][2], al[i][3],
                      base + ARR_B + aoff + i * 2304 + kk * 32);
            }
#pragma unroll
            for (int p = 0; p < 2; p++) {
                uint32_t r0, r1, r2, r3;
                ldsm4(r0, r1, r2, r3, base + 2 * ARR_B + boff + p * 2304 + kk * 32);
                bh[2*p][0] = r0; bh[2*p][1] = r1; bh[2*p+1][0] = r2; bh[2*p+1][1] = r3;
                ldsm4(r0, r1, r2, r3, base + 3 * ARR_B + boff + p * 2304 + kk * 32);
                bl[2*p][0] = r0; bl[2*p][1] = r1; bl[2*p+1][0] = r2; bl[2*p+1][1] = r3;
            }
#pragma unroll
            for (int i = 0; i < 2; i++)
#pragma unroll
                for (int j = 0; j < 4; j++) {
                    mma16816(c[i][j], ah[i][0], ah[i][1], ah[i][2], ah[i][3],
                             bh[j][0], bh[j][1]);
                    mma16816(c[i][j], ah[i][0], ah[i][1], ah[i][2], ah[i][3],
                             bl[j][0], bl[j][1]);
                    mma16816(c[i][j], al[i][0], al[i][1], al[i][2], al[i][3],
                             bh[j][0], bh[j][1]);
                }
        }
    }

#pragma unroll
    for (int i = 0; i < 2; i++) {
#pragma unroll
        for (int j = 0; j < 4; j++) {
            const int ncol = n0 + wn * 32 + j * 8 + (lane & 3) * 2;
#pragma unroll
            for (int half = 0; half < 2; half++) {
                const int row = m0 + wm * 32 + i * 16 + (lane >> 2) + half * 8;
                float vx = c[i][j][half * 2], vy = c[i][j][half * 2 + 1];
                if (mode == 0) {
                    const int p = ncol >> 10;
                    const float sc = (p == 0) ? 0.125f : 1.0f;
                    __nv_bfloat16* Th = (p == 0) ? g_qhi : ((p == 1) ? g_khi : g_vhi);
                    __nv_bfloat16* Tl = (p == 0) ? g_qlo : ((p == 1) ? g_klo : g_vlo);
                    const int h = (ncol & 1023) >> 6;
                    const int e = ncol & 63;
                    const int bb = row >> 11, ss = row & 2047;
                    __nv_bfloat16 hx, lx, hy, ly;
                    split_bf16(vx * sc, hx, lx);
                    split_bf16(vy * sc, hy, ly);
                    const size_t off = ((size_t)(bb * H_ + h) * S_ + ss) * HD_ + e;
                    *(uint32_t*)(Th + off) = pack2(hx, hy);
                    *(uint32_t*)(Tl + off) = pack2(lx, ly);
                } else {
                    float2 bv = *(const float2*)(bias + ncol);
                    float2 v = make_float2(vx + bv.x, vy + bv.y);
                    *(float2*)(outp + (size_t)row * D_ + ncol) = v;
                }
            }
        }
    }
#undef LOAD_STAGE
}

// ---------------------------------------------------------------------------
// Tensor-core causal flash attention (R5-verified, unchanged).
// ---------------------------------------------------------------------------
#define AT_LDB  144
#define AT_KSZ  (64 * AT_LDB)
#define AT_STAGE (4 * AT_KSZ)
#define AT_Q    (2 * 128 * AT_LDB)
#define AT_SMEM (AT_Q + 2 * AT_STAGE)

__global__ __launch_bounds__(256, 1)
void attn_mma() {
    extern __shared__ __align__(128) char smc[];
    const uint32_t sb = smem_u32(smc);
    const int tid = threadIdx.x;
    const int warp = tid >> 5, lane = tid & 31;
    const int bq = blockIdx.x, bh = blockIdx.y;
    const int q0 = bq * 128;

    const __nv_bfloat16* Qh = g_qhi + (size_t)bh * S_ * HD_;
    const __nv_bfloat16* Ql = g_qlo + (size_t)bh * S_ * HD_;
    const __nv_bfloat16* Kh = g_khi + (size_t)bh * S_ * HD_;
    const __nv_bfloat16* Kl = g_klo + (size_t)bh * S_ * HD_;
    const __nv_bfloat16* Vh = g_vhi + (size_t)bh * S_ * HD_;
    const __nv_bfloat16* Vl = g_vlo + (size_t)bh * S_ * HD_;

#pragma unroll
    for (int i = 0; i < 4; i++) {
        int idx = tid + i * 256;
        int r = idx >> 3, ch = idx & 7;
        size_t g = (size_t)(q0 + r) * HD_ + ch * 8;
        cp16(sb + r * AT_LDB + ch * 16, Qh + g);
        cp16(sb + 128 * AT_LDB + r * AT_LDB + ch * 16, Ql + g);
    }
    CP_COMMIT();

    const int ktmax = 2 * bq + 1;

#define LOAD_KV(kt, st) do { \
    uint32_t kb_ = sb + AT_Q + (uint32_t)(st) * AT_STAGE; \
    int t0_ = (kt) * 64; \
    _Pragma("unroll") \
    for (int i_ = 0; i_ < 2; i_++) { \
        int idx_ = tid + i_ * 256; \
        int r_ = idx_ >> 3, ch_ = idx_ & 7; \
        size_t g_ = (size_t)(t0_ + r_) * HD_ + ch_ * 8; \
        uint32_t s_ = (uint32_t)r_ * AT_LDB + (uint32_t)ch_ * 16; \
        cp16(kb_ + s_,              Kh + g_); \
        cp16(kb_ +     AT_KSZ + s_, Kl + g_); \
        cp16(kb_ + 2 * AT_KSZ + s_, Vh + g_); \
        cp16(kb_ + 3 * AT_KSZ + s_, Vl + g_); \
    } } while (0)

    LOAD_KV(0, 0); CP_COMMIT();
    CP_WAIT1();
    __syncthreads();

    uint32_t qh[4][4], ql[4][4];
    const uint32_t aoff = (uint32_t)(warp * 16 + (lane & 15)) * AT_LDB
                        + (uint32_t)(lane >> 4) * 16;
#pragma unroll
    for (int ks = 0; ks < 4; ks++) {
        ldsm4(qh[ks][0], qh[ks][1], qh[ks][2], qh[ks][3], sb + aoff + ks * 32);
        ldsm4(ql[ks][0], ql[ks][1], ql[ks][2], ql[ks][3],
              sb + 128 * AT_LDB + aoff + ks * 32);
    }
    if (1 <= ktmax) LOAD_KV(1, 1);
    CP_COMMIT();

    float oacc[8][4];
#pragma unroll
    for (int j = 0; j < 8; j++)
#pragma unroll
        for (int r = 0; r < 4; r++) oacc[j][r] = 0.f;
    float mrow[2] = {-1e30f, -1e30f};
    float lrow[2] = {0.f, 0.f};

    const int rg = q0 + warp * 16 + (lane >> 2);

    for (int kt = 0; kt <= ktmax; kt++) {
        CP_WAIT1();
        __syncthreads();
        const uint32_t kb = sb + AT_Q + (uint32_t)(kt & 1) * AT_STAGE;

        float sfr[8][4];
#pragma unroll
        for (int j = 0; j < 8; j++)
#pragma unroll
            for (int r = 0; r < 4; r++) sfr[j][r] = 0.f;

#pragma unroll
        for (int nb = 0; nb < 4; nb++) {
            const uint32_t brow = (uint32_t)(nb * 16 + (lane & 7) + ((lane >> 4) & 1) * 8) * AT_LDB
                                + (uint32_t)((lane >> 3) & 1) * 16;
#pragma unroll
            for (int ks = 0; ks < 4; ks++) {
                uint32_t h0, h1, h2, h3, l0, l1, l2, l3;
                ldsm4(h0, h1, h2, h3, kb + brow + ks * 32);
                ldsm4(l0, l1, l2, l3, kb + AT_KSZ + brow + ks * 32);
                mma16816(sfr[2*nb],   qh[ks][0], qh[ks][1], qh[ks][2], qh[ks][3], h0, h1);
                mma16816(sfr[2*nb],   qh[ks][0], qh[ks][1], qh[ks][2], qh[ks][3], l0, l1);
                mma16816(sfr[2*nb],   ql[ks][0], ql[ks][1], ql[ks][2], ql[ks][3], h0, h1);
                mma16816(sfr[2*nb+1], qh[ks][0], qh[ks][1], qh[ks][2], qh[ks][3], h2, h3);
                mma16816(sfr[2*nb+1], qh[ks][0], qh[ks][1], qh[ks][2], qh[ks][3], l2, l3);
                mma16816(sfr[2*nb+1], ql[ks][0], ql[ks][1], ql[ks][2], ql[ks][3], h2, h3);
            }
        }

        if (kt >= 2 * bq) {
            const int c0 = kt * 64 + (lane & 3) * 2;
#pragma unroll
            for (int j = 0; j < 8; j++) {
                const int c = c0 + j * 8;
                if (c     > rg)     sfr[j][0] = -1e30f;
                if (c + 1 > rg)     sfr[j][1] = -1e30f;
                if (c     > rg + 8) sfr[j][2] = -1e30f;
                if (c + 1 > rg + 8) sfr[j][3] = -1e30f;
            }
        }

#pragma unroll
        for (int r = 0; r < 2; r++) {
            float mx = -1e30f;
#pragma unroll
            for (int j = 0; j < 8; j++)
                mx = fmaxf(mx, fmaxf(sfr[j][2*r], sfr[j][2*r+1]));
            mx = fmaxf(mx, __shfl_xor_sync(0xffffffffu, mx, 1));
            mx = fmaxf(mx, __shfl_xor_sync(0xffffffffu, mx, 2));
            const float mnew = fmaxf(mrow[r], mx);
            const float corr = __expf(mrow[r] - mnew);
            mrow[r] = mnew;
            float sum = 0.f;
#pragma unroll
            for (int j = 0; j < 8; j++) {
                sfr[j][2*r]   = __expf(sfr[j][2*r]   - mnew);
                sfr[j][2*r+1] = __expf(sfr[j][2*r+1] - mnew);
                sum += sfr[j][2*r] + sfr[j][2*r+1];
            }
            sum += __shfl_xor_sync(0xffffffffu, sum, 1);
            sum += __shfl_xor_sync(0xffffffffu, sum, 2);
            lrow[r] = lrow[r] * corr + sum;
#pragma unroll
            for (int j = 0; j < 8; j++) {
                oacc[j][2*r]   *= corr;
                oacc[j][2*r+1] *= corr;
            }
        }

        uint32_t ph[4][4], pl[4][4];
#pragma unroll
        for (int ks = 0; ks < 4; ks++) {
#pragma unroll
            for (int idx = 0; idx < 4; idx++) {
                const float a = sfr[2*ks + (idx >> 1)][(idx & 1) * 2];
                const float b = sfr[2*ks + (idx >> 1)][(idx & 1) * 2 + 1];
                __nv_bfloat16 ahB, alB, bhB, blB;
                split_bf16(a, ahB, alB);
                split_bf16(b, bhB, blB);
                ph[ks][idx] = pack2(ahB, bhB);
                pl[ks][idx] = pack2(alB, blB);
            }
        }

        const uint32_t vb = kb + 2 * AT_KSZ;
#pragma unroll
        for (int ks = 0; ks < 4; ks++) {
            const uint32_t vrow = (uint32_t)(ks * 16 + (lane & 15)) * AT_LDB
                                + (uint32_t)(lane >> 4) * 16;
#pragma unroll
            for (int nb = 0; nb < 4; nb++) {
                uint32_t h0, h1, h2, h3, l0, l1, l2, l3;
                ldsm4t(h0, h1, h2, h3, vb + vrow + nb * 32);
                ldsm4t(l0, l1, l2, l3, vb + AT_KSZ + vrow + nb * 32);
                mma16816(oacc[2*nb],   ph[ks][0], ph[ks][1], ph[ks][2], ph[ks][3], h0, h1);
                mma16816(oacc[2*nb],   ph[ks][0], ph[ks][1], ph[ks][2], ph[ks][3], l0, l1);
                mma16816(oacc[2*nb],   pl[ks][0], pl[ks][1], pl[ks][2], pl[ks][3], h0, h1);
                mma16816(oacc[2*nb+1], ph[ks][0], ph[ks][1], ph[ks][2], ph[ks][3], h2, h3);
                mma16816(oacc[2*nb+1], ph[ks][0], ph[ks][1], ph[ks][2], ph[ks][3], l2, l3);
                mma16816(oacc[2*nb+1], pl[ks][0], pl[ks][1], pl[ks][2], pl[ks][3], h2, h3);
            }
        }

        __syncthreads();
        if (kt + 2 <= ktmax) LOAD_KV(kt + 2, kt & 1);
        CP_COMMIT();
    }

    const int b = bh >> 4, h = bh & 15;
    const float inv0 = 1.0f / lrow[0];
    const float inv1 = 1.0f / lrow[1];
#pragma unroll
    for (int j = 0; j < 8; j++) {
        const int e = j * 8 + (lane & 3) * 2;
#pragma unroll
        for (int r = 0; r < 2; r++) {
            const float inv = r ? inv1 : inv0;
            const float vx = oacc[j][2*r]     * inv;
            const float vy = oacc[j][2*r + 1] * inv;
            __nv_bfloat16 hx, lx, hy, ly;
            split_bf16(vx, hx, lx);
            split_bf16(vy, hy, ly);
            const size_t off = (size_t)(b * S_ + rg + r * 8) * KDIM + h * 64 + e;
            *(uint32_t*)(g_aohi + off) = pack2(hx, hy);
            *(uint32_t*)(g_aolo + off) = pack2(lx, ly);
        }
    }
#undef LOAD_KV
}

// ---------------------------------------------------------------------------
extern "C" void kernel_launch(void* const* d_in, const int* in_sizes, int n_in,
                              void* d_out, int out_size) {
    const float* x  = (const float*)d_in[0];
    const float* Wq = (const float*)d_in[1];
    const float* Wk = (const float*)d_in[2];
    const float* Wv = (const float*)d_in[3];
    const float* Wo = (const float*)d_in[4];
    const float* bo = (const float*)d_in[5];
    float* out = (float*)d_out;

    cudaFuncSetAttribute(gemm_mma, cudaFuncAttributeMaxDynamicSharedMemorySize,
                         (int)GEMM_SMEM);
    cudaFuncSetAttribute(attn_mma, cudaFuncAttributeMaxDynamicSharedMemorySize,
                         (int)AT_SMEM);

    conv_x_kernel<<<(M_TOT * KDIM) / (256 * 4), 256>>>(x);
    conv_wqkv_kernel<<<dim3(16, 16, 3), 256>>>(Wq, Wk, Wv);
    conv_wo_kernel<<<(D_ * KDIM) / (256 * 4), 256>>>(Wo);

    gemm_mma<<<dim3(NQKV / 128, M_TOT / 128), 512, GEMM_SMEM>>>(nullptr, nullptr, 0);
    attn_mma<<<dim3(S_ / 128, B_ * H_), 256, AT_SMEM>>>();
    gemm_mma<<<dim3(D_ / 128, M_TOT / 128), 512, GEMM_SMEM>>>(out, bo, 1);
}